// round 1
// baseline (speedup 1.0000x reference)
#include <cuda_runtime.h>
#include <math.h>

#define HEADS    16
#define HEAD_DIM 128
#define B_       2
#define T_       2048
#define DIM      2048
#define INNER    (HEADS * HEAD_DIM)   // 2048
#define QKV_N    (3 * INNER)          // 6144
#define MTOK     (B_ * T_)            // 4096

// Scratch (allocation-free rule: __device__ globals)
__device__ float g_qkv[(size_t)MTOK * QKV_N];   // [4096, 6144]
__device__ float g_attn[(size_t)MTOK * INNER];  // [4096, 2048]

// ---------------------------------------------------------------------------
// C[M,N] = A[M,K] @ B[N,K]^T   (both row-major, K contiguous)  — "NT" GEMM
// BM=BN=128, BK=16, 256 threads, 8x8 register tile per thread.
// Assumes M%128==0, N%128==0, K%16==0 (true for all our shapes).
// ---------------------------------------------------------------------------
__global__ __launch_bounds__(256, 2)
void sgemm_nt(const float* __restrict__ A, const float* __restrict__ Bm,
              float* __restrict__ C, int M, int N, int K)
{
    const int BM = 128, BN = 128, BK = 16;
    __shared__ float As[BK][BM];
    __shared__ float Bs[BK][BN];

    const int tid = threadIdx.x;
    const int tx  = tid & 15;     // 0..15  (N dir)
    const int ty  = tid >> 4;     // 0..15  (M dir)
    const int bm  = blockIdx.y * BM;
    const int bn  = blockIdx.x * BN;

    float acc[8][8];
#pragma unroll
    for (int i = 0; i < 8; i++)
#pragma unroll
        for (int j = 0; j < 8; j++) acc[i][j] = 0.f;

    for (int k0 = 0; k0 < K; k0 += BK) {
        // Load A tile (128x16) transposed into As[k][m]
#pragma unroll
        for (int i = 0; i < 2; i++) {
            int idx = tid + i * 256;          // 0..511 float4 slots
            int r   = idx >> 2;               // 0..127
            int c4  = (idx & 3) << 2;         // 0,4,8,12
            float4 v = *(const float4*)&A[(size_t)(bm + r) * K + k0 + c4];
            As[c4 + 0][r] = v.x;
            As[c4 + 1][r] = v.y;
            As[c4 + 2][r] = v.z;
            As[c4 + 3][r] = v.w;
        }
        // Load B tile (128x16) transposed into Bs[k][n]
#pragma unroll
        for (int i = 0; i < 2; i++) {
            int idx = tid + i * 256;
            int r   = idx >> 2;
            int c4  = (idx & 3) << 2;
            float4 v = *(const float4*)&Bm[(size_t)(bn + r) * K + k0 + c4];
            Bs[c4 + 0][r] = v.x;
            Bs[c4 + 1][r] = v.y;
            Bs[c4 + 2][r] = v.z;
            Bs[c4 + 3][r] = v.w;
        }
        __syncthreads();

#pragma unroll
        for (int kk = 0; kk < BK; kk++) {
            float a[8], b[8];
            *(float4*)&a[0] = *(const float4*)&As[kk][ty * 8];
            *(float4*)&a[4] = *(const float4*)&As[kk][ty * 8 + 4];
            *(float4*)&b[0] = *(const float4*)&Bs[kk][tx * 8];
            *(float4*)&b[4] = *(const float4*)&Bs[kk][tx * 8 + 4];
#pragma unroll
            for (int i = 0; i < 8; i++)
#pragma unroll
                for (int j = 0; j < 8; j++)
                    acc[i][j] += a[i] * b[j];
        }
        __syncthreads();
    }

#pragma unroll
    for (int i = 0; i < 8; i++) {
        size_t r = (size_t)(bm + ty * 8 + i);
#pragma unroll
        for (int j = 0; j < 8; j += 4) {
            float4 v = make_float4(acc[i][j], acc[i][j + 1], acc[i][j + 2], acc[i][j + 3]);
            *(float4*)&C[r * N + bn + tx * 8 + j] = v;
        }
    }
}

// ---------------------------------------------------------------------------
// RoPE in-place on q and k halves of g_qkv. One thread per (sec,b,t,h,i) pair.
// idx = (((sec*B + b)*T + t)*HEADS + h)*64 + i ; total = 2*2*2048*16*64 = 2^23
// ---------------------------------------------------------------------------
__global__ void rope_kernel(float* __restrict__ qkv)
{
    int idx = blockIdx.x * 256 + threadIdx.x;
    int i   = idx & 63;
    int h   = (idx >> 6) & 15;
    int t   = (idx >> 10) & 2047;
    int b   = (idx >> 21) & 1;
    int sec = (idx >> 22) & 1;   // 0=q, 1=k

    // inv_freq = 10000^{-(2i/128)} = exp(-i * ln(10000)/64); do in double for safety
    double dinv = exp(-(double)i * 0.14391156831212787);   // ln(1e4)/64
    float  ang  = (float)((double)t * dinv);
    float sn, cs;
    sincosf(ang, &sn, &cs);

    float* p = qkv + (size_t)(b * T_ + t) * QKV_N + sec * INNER + h * HEAD_DIM + i;
    float x1 = p[0];
    float x2 = p[64];
    p[0]  = x1 * cs - x2 * sn;
    p[64] = x2 * cs + x1 * sn;
}

// ---------------------------------------------------------------------------
// Causal flash attention, fp32.
// Block: 256 threads (16x16), handles BQ=64 query rows for one (b,h).
// Smem: Qs,Ks stored d-major [128][68]; Vs [64][132]; Ps [64][68].
// Each thread: 4 S-rows (ty) x 4 S-cols (tx); O tile 4 rows x 8 cols.
// ---------------------------------------------------------------------------
#define BQ  64
#define BKV 64
#define QS_LD 68
#define VS_LD 132
#define ATTN_SMEM ((128*QS_LD*2 + BKV*VS_LD + BQ*QS_LD) * 4)

__global__ __launch_bounds__(256)
void attn_kernel(const float* __restrict__ qkv, float* __restrict__ attn_out)
{
    extern __shared__ float sm[];
    float* Qs = sm;                         // [128][68]  (d-major)
    float* Ks = Qs + 128 * QS_LD;           // [128][68]  (d-major)
    float* Vs = Ks + 128 * QS_LD;           // [64][132]  (kv-major)
    float* Ps = Vs + BKV * VS_LD;           // [64][68]

    const int tid = threadIdx.x;
    const int tx  = tid & 15;
    const int ty  = tid >> 4;
    const int qb  = blockIdx.x;
    const int b   = blockIdx.y >> 4;
    const int h   = blockIdx.y & 15;
    const int q0  = qb * BQ;
    const float scale = 0.08838834764831843f;  // 1/sqrt(128)

    const float* qptr = qkv + (size_t)b * T_ * QKV_N + h * HEAD_DIM;
    const float* kptr = qptr + INNER;
    const float* vptr = qptr + 2 * INNER;

    // Load Q tile (64x128) transposed with scale folded in
    for (int idx = tid; idx < BQ * 32; idx += 256) {
        int r  = idx >> 5;
        int c4 = (idx & 31) << 2;
        float4 v = *(const float4*)(qptr + (size_t)(q0 + r) * QKV_N + c4);
        Qs[(c4 + 0) * QS_LD + r] = v.x * scale;
        Qs[(c4 + 1) * QS_LD + r] = v.y * scale;
        Qs[(c4 + 2) * QS_LD + r] = v.z * scale;
        Qs[(c4 + 3) * QS_LD + r] = v.w * scale;
    }

    float m_r[4], l_r[4], o[4][8];
#pragma unroll
    for (int i = 0; i < 4; i++) {
        m_r[i] = -INFINITY;
        l_r[i] = 0.f;
#pragma unroll
        for (int c = 0; c < 8; c++) o[i][c] = 0.f;
    }
    __syncthreads();

    for (int kb = 0; kb <= qb; kb++) {
        int k0 = kb * BKV;
        // Load K (transposed d-major) and V (kv-major) tiles
        for (int idx = tid; idx < BKV * 32; idx += 256) {
            int r  = idx >> 5;
            int c4 = (idx & 31) << 2;
            float4 v = *(const float4*)(kptr + (size_t)(k0 + r) * QKV_N + c4);
            Ks[(c4 + 0) * QS_LD + r] = v.x;
            Ks[(c4 + 1) * QS_LD + r] = v.y;
            Ks[(c4 + 2) * QS_LD + r] = v.z;
            Ks[(c4 + 3) * QS_LD + r] = v.w;
            float4 w = *(const float4*)(vptr + (size_t)(k0 + r) * QKV_N + c4);
            *(float4*)(Vs + r * VS_LD + c4) = w;
        }
        __syncthreads();

        // S = (Q*scale) @ K^T  : 4x4 per thread, outer product over d
        float s[4][4];
#pragma unroll
        for (int i = 0; i < 4; i++)
#pragma unroll
            for (int j = 0; j < 4; j++) s[i][j] = 0.f;

#pragma unroll 4
        for (int d = 0; d < 128; d++) {
            float4 a  = *(const float4*)(Qs + d * QS_LD + ty * 4);
            float4 bb = *(const float4*)(Ks + d * QS_LD + tx * 4);
            float av[4] = {a.x, a.y, a.z, a.w};
            float bv[4] = {bb.x, bb.y, bb.z, bb.w};
#pragma unroll
            for (int i = 0; i < 4; i++)
#pragma unroll
                for (int j = 0; j < 4; j++)
                    s[i][j] += av[i] * bv[j];
        }

        // Causal mask (only on diagonal block)
        if (kb == qb) {
#pragma unroll
            for (int i = 0; i < 4; i++)
#pragma unroll
                for (int j = 0; j < 4; j++)
                    if (k0 + tx * 4 + j > q0 + ty * 4 + i) s[i][j] = -INFINITY;
        }

        // Online softmax: reduce over 16 tx lanes (xor 1,2,4,8 stays in group)
#pragma unroll
        for (int i = 0; i < 4; i++) {
            float mx = fmaxf(fmaxf(s[i][0], s[i][1]), fmaxf(s[i][2], s[i][3]));
#pragma unroll
            for (int off = 1; off < 16; off <<= 1)
                mx = fmaxf(mx, __shfl_xor_sync(0xffffffffu, mx, off));
            float mnew = fmaxf(m_r[i], mx);
            float corr = __expf(m_r[i] - mnew);   // exp(-inf)=0 on first iter
            float rs = 0.f;
#pragma unroll
            for (int j = 0; j < 4; j++) {
                float p = __expf(s[i][j] - mnew);  // masked -> exp(-inf)=0
                s[i][j] = p;
                rs += p;
            }
#pragma unroll
            for (int off = 1; off < 16; off <<= 1)
                rs += __shfl_xor_sync(0xffffffffu, rs, off);
            l_r[i] = l_r[i] * corr + rs;
            m_r[i] = mnew;
#pragma unroll
            for (int c = 0; c < 8; c++) o[i][c] *= corr;
            *(float4*)(Ps + (ty * 4 + i) * QS_LD + tx * 4) =
                make_float4(s[i][0], s[i][1], s[i][2], s[i][3]);
        }
        __syncthreads();

        // O += P @ V : each thread 4 rows x 8 cols
#pragma unroll 2
        for (int j = 0; j < BKV; j++) {
            float p0 = Ps[(ty * 4 + 0) * QS_LD + j];
            float p1 = Ps[(ty * 4 + 1) * QS_LD + j];
            float p2 = Ps[(ty * 4 + 2) * QS_LD + j];
            float p3 = Ps[(ty * 4 + 3) * QS_LD + j];
            float4 v0 = *(const float4*)(Vs + j * VS_LD + tx * 8);
            float4 v1 = *(const float4*)(Vs + j * VS_LD + tx * 8 + 4);
            float vv[8] = {v0.x, v0.y, v0.z, v0.w, v1.x, v1.y, v1.z, v1.w};
            float pp[4] = {p0, p1, p2, p3};
#pragma unroll
            for (int i = 0; i < 4; i++)
#pragma unroll
                for (int c = 0; c < 8; c++)
                    o[i][c] += pp[i] * vv[c];
        }
        __syncthreads();
    }

    // Epilogue: normalize and store to [b, t, h*128 + d]
#pragma unroll
    for (int i = 0; i < 4; i++) {
        float inv = 1.f / l_r[i];
        int t = q0 + ty * 4 + i;
        float* op = attn_out + (size_t)(b * T_ + t) * INNER + h * HEAD_DIM + tx * 8;
        *(float4*)op       = make_float4(o[i][0] * inv, o[i][1] * inv, o[i][2] * inv, o[i][3] * inv);
        *(float4*)(op + 4) = make_float4(o[i][4] * inv, o[i][5] * inv, o[i][6] * inv, o[i][7] * inv);
    }
}

// ---------------------------------------------------------------------------
extern "C" void kernel_launch(void* const* d_in, const int* in_sizes, int n_in,
                              void* d_out, int out_size)
{
    const float* x      = (const float*)d_in[0];   // [2,2048,2048]
    const float* W_qkv  = (const float*)d_in[1];   // [6144,2048]
    const float* W_proj = (const float*)d_in[2];   // [2048,2048]
    float* out = (float*)d_out;                    // [2,2048,2048]

    float *qkv_ptr, *attn_ptr;
    cudaGetSymbolAddress((void**)&qkv_ptr, g_qkv);
    cudaGetSymbolAddress((void**)&attn_ptr, g_attn);

    // Opt in to >48KB dynamic smem for the attention kernel (idempotent).
    cudaFuncSetAttribute(attn_kernel, cudaFuncAttributeMaxDynamicSharedMemorySize,
                         ATTN_SMEM);

    // 1) qkv = x @ W_qkv^T   : M=4096, N=6144, K=2048
    sgemm_nt<<<dim3(QKV_N / 128, MTOK / 128), 256>>>(x, W_qkv, qkv_ptr,
                                                     MTOK, QKV_N, DIM);
    // 2) RoPE in place on q,k
    rope_kernel<<<(2 * B_ * T_ * HEADS * 64) / 256, 256>>>(qkv_ptr);

    // 3) causal flash attention
    attn_kernel<<<dim3(T_ / BQ, B_ * HEADS), 256, ATTN_SMEM>>>(qkv_ptr, attn_ptr);

    // 4) out = attn @ W_proj^T : M=4096, N=2048, K=2048
    sgemm_nt<<<dim3(INNER / 128, MTOK / 128), 256>>>(attn_ptr, W_proj, out,
                                                     MTOK, INNER, DIM);
}

// round 3
// speedup vs baseline: 1.6956x; 1.6956x over previous
#include <cuda_runtime.h>
#include <cuda_bf16.h>
#include <math.h>
#include <cstdint>

#define HEADS    16
#define HEAD_DIM 128
#define B_       2
#define T_       2048
#define DIM      2048
#define INNER    (HEADS * HEAD_DIM)   // 2048
#define QKV_N    (3 * INNER)          // 6144
#define MTOK     (B_ * T_)            // 4096

// ---------------------------------------------------------------------------
// Scratch (allocation-free rule: __device__ globals)
// ---------------------------------------------------------------------------
__device__ float g_qkv[(size_t)MTOK * QKV_N];    // fp32 qkv
__device__ float g_attn[(size_t)MTOK * INNER];   // fp32 attention out
__device__ __nv_bfloat16 g_xh[(size_t)MTOK * DIM],  g_xl[(size_t)MTOK * DIM];
__device__ __nv_bfloat16 g_wqh[(size_t)QKV_N * DIM], g_wql[(size_t)QKV_N * DIM];
__device__ __nv_bfloat16 g_wph[(size_t)INNER * DIM], g_wpl[(size_t)INNER * DIM];
__device__ __nv_bfloat16 g_ah[(size_t)MTOK * INNER], g_al[(size_t)MTOK * INNER];

// ---------------------------------------------------------------------------
// PTX helpers (baseline ISA only — works on plain sm_103 target)
// ---------------------------------------------------------------------------
__device__ __forceinline__ uint32_t smem_to_u32(const void* p) {
    uint32_t a;
    asm("{ .reg .u64 t; cvta.to.shared.u64 t, %1; cvt.u32.u64 %0, t; }"
        : "=r"(a) : "l"(p));
    return a;
}
__device__ __forceinline__ void cp_async16(uint32_t dst, const void* src) {
    asm volatile("cp.async.cg.shared.global [%0], [%1], 16;" :: "r"(dst), "l"(src));
}
#define CP_COMMIT() asm volatile("cp.async.commit_group;" ::: "memory")
#define CP_WAIT(n)  asm volatile("cp.async.wait_group %0;" :: "n"(n) : "memory")

#define LDSM_X4(r0, r1, r2, r3, addr) \
    asm volatile("ldmatrix.sync.aligned.m8n8.x4.shared.b16 {%0,%1,%2,%3}, [%4];" \
        : "=r"(r0), "=r"(r1), "=r"(r2), "=r"(r3) : "r"(addr))

__device__ __forceinline__ void mma_bf16(float* c, const uint32_t* a, const uint32_t* b)
{
    asm volatile(
        "mma.sync.aligned.m16n8k16.row.col.f32.bf16.bf16.f32 "
        "{%0,%1,%2,%3}, {%4,%5,%6,%7}, {%8,%9}, {%0,%1,%2,%3};"
        : "+f"(c[0]), "+f"(c[1]), "+f"(c[2]), "+f"(c[3])
        : "r"(a[0]), "r"(a[1]), "r"(a[2]), "r"(a[3]), "r"(b[0]), "r"(b[1]));
}

// ---------------------------------------------------------------------------
// Split fp32 -> (hi bf16, lo bf16)
// ---------------------------------------------------------------------------
__global__ void split_kernel(const float* __restrict__ src,
                             __nv_bfloat16* __restrict__ hi,
                             __nv_bfloat16* __restrict__ lo, int n4)
{
    int i = blockIdx.x * 256 + threadIdx.x;
    if (i >= n4) return;
    float4 v = ((const float4*)src)[i];
    float f[4] = {v.x, v.y, v.z, v.w};
    __nv_bfloat162 h2[2], l2[2];
#pragma unroll
    for (int j = 0; j < 2; j++) {
        __nv_bfloat16 h0 = __float2bfloat16(f[2 * j]);
        __nv_bfloat16 h1 = __float2bfloat16(f[2 * j + 1]);
        __nv_bfloat16 l0 = __float2bfloat16(f[2 * j] - __bfloat162float(h0));
        __nv_bfloat16 l1 = __float2bfloat16(f[2 * j + 1] - __bfloat162float(h1));
        h2[j] = __nv_bfloat162(h0, h1);
        l2[j] = __nv_bfloat162(l0, l1);
    }
    ((__nv_bfloat162*)hi)[2 * i]     = h2[0];
    ((__nv_bfloat162*)hi)[2 * i + 1] = h2[1];
    ((__nv_bfloat162*)lo)[2 * i]     = l2[0];
    ((__nv_bfloat162*)lo)[2 * i + 1] = l2[1];
}

// ---------------------------------------------------------------------------
// HMMA GEMM: C[M,N](fp32) = (Ah+Al)[M,K] @ (Bh+Bl)[N,K]^T, 3-term bf16 split.
// BM=BN=128, BK=32, 256 threads (8 warps, 2x4), warp tile 64x32.
// cp.async double-buffered smem, padded stride-40 layout (conflict-free ldsm).
// ---------------------------------------------------------------------------
#define GBM 128
#define GBN 128
#define GBK 32
#define LDA 40                              // bf16 elems per row slot
#define MAT_BYTES (128 * LDA * 2)           // 10240
#define STAGE_BYTES (4 * MAT_BYTES)         // 40960
#define GEMM_SMEM (2 * STAGE_BYTES)         // 81920

__device__ __forceinline__ void issue_stage(
    const __nv_bfloat16* __restrict__ Ah, const __nv_bfloat16* __restrict__ Al,
    const __nv_bfloat16* __restrict__ Bh, const __nv_bfloat16* __restrict__ Bl,
    size_t bm, size_t bn, int K, int k0, uint32_t sbase, int tid)
{
#pragma unroll
    for (int i = 0; i < 2; i++) {
        int idx = tid + i * 256;            // 0..511
        int r   = idx >> 2;                 // 0..127
        int c   = (idx & 3) << 3;           // 0,8,16,24
        uint32_t doff = (uint32_t)(r * LDA + c) * 2;
        size_t asrc = (bm + (size_t)r) * K + k0 + c;
        size_t bsrc = (bn + (size_t)r) * K + k0 + c;
        cp_async16(sbase + doff,                 Ah + asrc);
        cp_async16(sbase + MAT_BYTES + doff,     Al + asrc);
        cp_async16(sbase + 2 * MAT_BYTES + doff, Bh + bsrc);
        cp_async16(sbase + 3 * MAT_BYTES + doff, Bl + bsrc);
    }
}

__global__ __launch_bounds__(256, 1)
void gemm_bf16x3(const __nv_bfloat16* __restrict__ Ah, const __nv_bfloat16* __restrict__ Al,
                 const __nv_bfloat16* __restrict__ Bh, const __nv_bfloat16* __restrict__ Bl,
                 float* __restrict__ C, int M, int N, int K)
{
    extern __shared__ char smem[];
    const uint32_t s0 = smem_to_u32(smem);

    const int tid = threadIdx.x;
    const int wid = tid >> 5;
    const int l   = tid & 31;
    const int warp_m = wid & 1;             // 0..1 -> 64 rows each
    const int warp_n = wid >> 1;            // 0..3 -> 32 cols each
    const size_t bm = (size_t)blockIdx.y * GBM;
    const size_t bn = (size_t)blockIdx.x * GBN;

    float acc[4][4][4];
#pragma unroll
    for (int mi = 0; mi < 4; mi++)
#pragma unroll
        for (int ni = 0; ni < 4; ni++)
#pragma unroll
            for (int e = 0; e < 4; e++) acc[mi][ni][e] = 0.f;

    const int S = K / GBK;
    issue_stage(Ah, Al, Bh, Bl, bm, bn, K, 0, s0, tid);
    CP_COMMIT();

    // Per-lane ldmatrix address components (element offsets within a matrix)
    const int a_row = warp_m * 64 + (l & 15);
    const int a_ch  = (l >> 4) * 8;         // k sub-chunk 0/8
    const int g     = l >> 3;
    const int b_row = warp_n * 32 + ((g >> 1) << 3) + (l & 7);
    const int b_ch  = (g & 1) << 3;

    for (int s = 0; s < S; s++) {
        if (s + 1 < S) {
            issue_stage(Ah, Al, Bh, Bl, bm, bn, K, (s + 1) * GBK,
                        s0 + ((s + 1) & 1) * STAGE_BYTES, tid);
            CP_COMMIT();
            CP_WAIT(1);
        } else {
            CP_WAIT(0);
        }
        __syncthreads();

        const uint32_t ahB = s0 + (s & 1) * STAGE_BYTES;
        const uint32_t alB = ahB + MAT_BYTES;
        const uint32_t bhB = ahB + 2 * MAT_BYTES;
        const uint32_t blB = ahB + 3 * MAT_BYTES;

#pragma unroll
        for (int ks = 0; ks < 2; ks++) {
            const int kc = ks * 16;
            uint32_t ah[4][4], al[4][4], bh[4][2], bl[4][2];
#pragma unroll
            for (int mi = 0; mi < 4; mi++) {
                uint32_t off = (uint32_t)((a_row + mi * 16) * LDA + kc + a_ch) * 2;
                LDSM_X4(ah[mi][0], ah[mi][1], ah[mi][2], ah[mi][3], ahB + off);
                LDSM_X4(al[mi][0], al[mi][1], al[mi][2], al[mi][3], alB + off);
            }
#pragma unroll
            for (int nt = 0; nt < 2; nt++) {
                uint32_t off = (uint32_t)((b_row + nt * 16) * LDA + kc + b_ch) * 2;
                LDSM_X4(bh[2 * nt][0], bh[2 * nt][1], bh[2 * nt + 1][0], bh[2 * nt + 1][1], bhB + off);
                LDSM_X4(bl[2 * nt][0], bl[2 * nt][1], bl[2 * nt + 1][0], bl[2 * nt + 1][1], blB + off);
            }
#pragma unroll
            for (int mi = 0; mi < 4; mi++)
#pragma unroll
                for (int ni = 0; ni < 4; ni++)
                    mma_bf16(acc[mi][ni], ah[mi], bh[ni]);
#pragma unroll
            for (int mi = 0; mi < 4; mi++)
#pragma unroll
                for (int ni = 0; ni < 4; ni++)
                    mma_bf16(acc[mi][ni], al[mi], bh[ni]);
#pragma unroll
            for (int mi = 0; mi < 4; mi++)
#pragma unroll
                for (int ni = 0; ni < 4; ni++)
                    mma_bf16(acc[mi][ni], ah[mi], bl[ni]);
        }
        __syncthreads();
    }

    // Epilogue: acc[mi][ni] rows = 16*mi + l/4 (+8), cols = 8*ni + 2*(l%4)
    const size_t row0 = bm + warp_m * 64 + (l >> 2);
    const int    col0 = (int)bn + warp_n * 32 + 2 * (l & 3);
#pragma unroll
    for (int mi = 0; mi < 4; mi++) {
#pragma unroll
        for (int ni = 0; ni < 4; ni++) {
            float* p0 = C + (row0 + mi * 16) * N + col0 + ni * 8;
            float* p1 = p0 + 8 * (size_t)N;
            *(float2*)p0 = make_float2(acc[mi][ni][0], acc[mi][ni][1]);
            *(float2*)p1 = make_float2(acc[mi][ni][2], acc[mi][ni][3]);
        }
    }
}

// ---------------------------------------------------------------------------
// RoPE in-place on q and k halves of g_qkv (fp32, fast path).
// ---------------------------------------------------------------------------
__global__ void rope_kernel(float* __restrict__ qkv)
{
    int idx = blockIdx.x * 256 + threadIdx.x;
    int i   = idx & 63;
    int t   = (idx >> 10) & 2047;
    int b   = (idx >> 21) & 1;
    int sec = (idx >> 22) & 1;   // 0=q, 1=k

    int h   = (idx >> 6) & 15;

    // inv_freq = 10000^{-i/64} = 2^{-i * log2(1e4)/64}
    float inv = exp2f(-(float)i * 0.20761871929656223f);
    float ang = (float)t * inv;
    float sn, cs;
    sincosf(ang, &sn, &cs);

    float* p = qkv + (size_t)(b * T_ + t) * QKV_N + sec * INNER + h * HEAD_DIM + i;
    float x1 = p[0];
    float x2 = p[64];
    p[0]  = x1 * cs - x2 * sn;
    p[64] = x2 * cs + x1 * sn;
}

// ---------------------------------------------------------------------------
// Causal flash attention, fp32 SIMT (unchanged — converts to HMMA next round)
// ---------------------------------------------------------------------------
#define BQ  64
#define BKV 64
#define QS_LD 68
#define VS_LD 132
#define ATTN_SMEM ((128*QS_LD*2 + BKV*VS_LD + BQ*QS_LD) * 4)

__global__ __launch_bounds__(256)
void attn_kernel(const float* __restrict__ qkv, float* __restrict__ attn_out)
{
    extern __shared__ float sm[];
    float* Qs = sm;
    float* Ks = Qs + 128 * QS_LD;
    float* Vs = Ks + 128 * QS_LD;
    float* Ps = Vs + BKV * VS_LD;

    const int tid = threadIdx.x;
    const int tx  = tid & 15;
    const int ty  = tid >> 4;
    const int qb  = blockIdx.x;
    const int b   = blockIdx.y >> 4;
    const int h   = blockIdx.y & 15;
    const int q0  = qb * BQ;
    const float scale = 0.08838834764831843f;

    const float* qptr = qkv + (size_t)b * T_ * QKV_N + h * HEAD_DIM;
    const float* kptr = qptr + INNER;
    const float* vptr = qptr + 2 * INNER;

    for (int idx = tid; idx < BQ * 32; idx += 256) {
        int r  = idx >> 5;
        int c4 = (idx & 31) << 2;
        float4 v = *(const float4*)(qptr + (size_t)(q0 + r) * QKV_N + c4);
        Qs[(c4 + 0) * QS_LD + r] = v.x * scale;
        Qs[(c4 + 1) * QS_LD + r] = v.y * scale;
        Qs[(c4 + 2) * QS_LD + r] = v.z * scale;
        Qs[(c4 + 3) * QS_LD + r] = v.w * scale;
    }

    float m_r[4], l_r[4], o[4][8];
#pragma unroll
    for (int i = 0; i < 4; i++) {
        m_r[i] = -INFINITY;
        l_r[i] = 0.f;
#pragma unroll
        for (int c = 0; c < 8; c++) o[i][c] = 0.f;
    }
    __syncthreads();

    for (int kb = 0; kb <= qb; kb++) {
        int k0 = kb * BKV;
        for (int idx = tid; idx < BKV * 32; idx += 256) {
            int r  = idx >> 5;
            int c4 = (idx & 31) << 2;
            float4 v = *(const float4*)(kptr + (size_t)(k0 + r) * QKV_N + c4);
            Ks[(c4 + 0) * QS_LD + r] = v.x;
            Ks[(c4 + 1) * QS_LD + r] = v.y;
            Ks[(c4 + 2) * QS_LD + r] = v.z;
            Ks[(c4 + 3) * QS_LD + r] = v.w;
            float4 w = *(const float4*)(vptr + (size_t)(k0 + r) * QKV_N + c4);
            *(float4*)(Vs + r * VS_LD + c4) = w;
        }
        __syncthreads();

        float s[4][4];
#pragma unroll
        for (int i = 0; i < 4; i++)
#pragma unroll
            for (int j = 0; j < 4; j++) s[i][j] = 0.f;

#pragma unroll 4
        for (int d = 0; d < 128; d++) {
            float4 a  = *(const float4*)(Qs + d * QS_LD + ty * 4);
            float4 bb = *(const float4*)(Ks + d * QS_LD + tx * 4);
            float av[4] = {a.x, a.y, a.z, a.w};
            float bv[4] = {bb.x, bb.y, bb.z, bb.w};
#pragma unroll
            for (int i = 0; i < 4; i++)
#pragma unroll
                for (int j = 0; j < 4; j++)
                    s[i][j] += av[i] * bv[j];
        }

        if (kb == qb) {
#pragma unroll
            for (int i = 0; i < 4; i++)
#pragma unroll
                for (int j = 0; j < 4; j++)
                    if (k0 + tx * 4 + j > q0 + ty * 4 + i) s[i][j] = -INFINITY;
        }

#pragma unroll
        for (int i = 0; i < 4; i++) {
            float mx = fmaxf(fmaxf(s[i][0], s[i][1]), fmaxf(s[i][2], s[i][3]));
#pragma unroll
            for (int off = 1; off < 16; off <<= 1)
                mx = fmaxf(mx, __shfl_xor_sync(0xffffffffu, mx, off));
            float mnew = fmaxf(m_r[i], mx);
            float corr = __expf(m_r[i] - mnew);
            float rs = 0.f;
#pragma unroll
            for (int j = 0; j < 4; j++) {
                float p = __expf(s[i][j] - mnew);
                s[i][j] = p;
                rs += p;
            }
#pragma unroll
            for (int off = 1; off < 16; off <<= 1)
                rs += __shfl_xor_sync(0xffffffffu, rs, off);
            l_r[i] = l_r[i] * corr + rs;
            m_r[i] = mnew;
#pragma unroll
            for (int c = 0; c < 8; c++) o[i][c] *= corr;
            *(float4*)(Ps + (ty * 4 + i) * QS_LD + tx * 4) =
                make_float4(s[i][0], s[i][1], s[i][2], s[i][3]);
        }
        __syncthreads();

#pragma unroll 2
        for (int j = 0; j < BKV; j++) {
            float p0 = Ps[(ty * 4 + 0) * QS_LD + j];
            float p1 = Ps[(ty * 4 + 1) * QS_LD + j];
            float p2 = Ps[(ty * 4 + 2) * QS_LD + j];
            float p3 = Ps[(ty * 4 + 3) * QS_LD + j];
            float4 v0 = *(const float4*)(Vs + j * VS_LD + tx * 8);
            float4 v1 = *(const float4*)(Vs + j * VS_LD + tx * 8 + 4);
            float vv[8] = {v0.x, v0.y, v0.z, v0.w, v1.x, v1.y, v1.z, v1.w};
            float pp[4] = {p0, p1, p2, p3};
#pragma unroll
            for (int i = 0; i < 4; i++)
#pragma unroll
                for (int c = 0; c < 8; c++)
                    o[i][c] += pp[i] * vv[c];
        }
        __syncthreads();
    }

#pragma unroll
    for (int i = 0; i < 4; i++) {
        float inv = 1.f / l_r[i];
        int t = q0 + ty * 4 + i;
        float* op = attn_out + (size_t)(b * T_ + t) * INNER + h * HEAD_DIM + tx * 8;
        *(float4*)op       = make_float4(o[i][0] * inv, o[i][1] * inv, o[i][2] * inv, o[i][3] * inv);
        *(float4*)(op + 4) = make_float4(o[i][4] * inv, o[i][5] * inv, o[i][6] * inv, o[i][7] * inv);
    }
}

// ---------------------------------------------------------------------------
extern "C" void kernel_launch(void* const* d_in, const int* in_sizes, int n_in,
                              void* d_out, int out_size)
{
    const float* x      = (const float*)d_in[0];   // [2,2048,2048]
    const float* W_qkv  = (const float*)d_in[1];   // [6144,2048]
    const float* W_proj = (const float*)d_in[2];   // [2048,2048]
    float* out = (float*)d_out;                    // [2,2048,2048]

    float *qkv_ptr, *attn_ptr;
    __nv_bfloat16 *xh, *xl, *wqh, *wql, *wph, *wpl, *ah, *al;
    cudaGetSymbolAddress((void**)&qkv_ptr, g_qkv);
    cudaGetSymbolAddress((void**)&attn_ptr, g_attn);
    cudaGetSymbolAddress((void**)&xh, g_xh);
    cudaGetSymbolAddress((void**)&xl, g_xl);
    cudaGetSymbolAddress((void**)&wqh, g_wqh);
    cudaGetSymbolAddress((void**)&wql, g_wql);
    cudaGetSymbolAddress((void**)&wph, g_wph);
    cudaGetSymbolAddress((void**)&wpl, g_wpl);
    cudaGetSymbolAddress((void**)&ah, g_ah);
    cudaGetSymbolAddress((void**)&al, g_al);

    cudaFuncSetAttribute(gemm_bf16x3, cudaFuncAttributeMaxDynamicSharedMemorySize,
                         GEMM_SMEM);
    cudaFuncSetAttribute(attn_kernel, cudaFuncAttributeMaxDynamicSharedMemorySize,
                         ATTN_SMEM);

    // Split inputs/weights into bf16 hi/lo
    split_kernel<<<(MTOK * DIM / 4) / 256, 256>>>(x, xh, xl, MTOK * DIM / 4);
    split_kernel<<<(QKV_N * DIM / 4) / 256, 256>>>(W_qkv, wqh, wql, QKV_N * DIM / 4);
    split_kernel<<<(INNER * DIM / 4) / 256, 256>>>(W_proj, wph, wpl, INNER * DIM / 4);

    // 1) qkv = x @ W_qkv^T : M=4096, N=6144, K=2048 (HMMA)
    gemm_bf16x3<<<dim3(QKV_N / GBN, MTOK / GBM), 256, GEMM_SMEM>>>(
        xh, xl, wqh, wql, qkv_ptr, MTOK, QKV_N, DIM);

    // 2) RoPE in place on q,k
    rope_kernel<<<(2 * B_ * T_ * HEADS * 64) / 256, 256>>>(qkv_ptr);

    // 3) causal flash attention (SIMT fp32)
    attn_kernel<<<dim3(T_ / BQ, B_ * HEADS), 256, ATTN_SMEM>>>(qkv_ptr, attn_ptr);

    // 4) split attention output, then out = attn @ W_proj^T (HMMA)
    split_kernel<<<(MTOK * INNER / 4) / 256, 256>>>(attn_ptr, ah, al, MTOK * INNER / 4);
    gemm_bf16x3<<<dim3(INNER / GBN, MTOK / GBM), 256, GEMM_SMEM>>>(
        ah, al, wph, wpl, out, MTOK, INNER, DIM);
}

// round 4
// speedup vs baseline: 3.0397x; 1.7927x over previous
#include <cuda_runtime.h>
#include <cuda_bf16.h>
#include <math.h>
#include <cstdint>

#define HEADS    16
#define HEAD_DIM 128
#define B_       2
#define T_       2048
#define DIM      2048
#define INNER    (HEADS * HEAD_DIM)   // 2048
#define QKV_N    (3 * INNER)          // 6144
#define MTOK     (B_ * T_)            // 4096

// ---------------------------------------------------------------------------
// Scratch (allocation-free rule: __device__ globals)
// ---------------------------------------------------------------------------
__device__ float g_qkv[(size_t)MTOK * QKV_N];    // fp32 qkv (pre-rope)
__device__ __nv_bfloat16 g_qkvh[(size_t)MTOK * QKV_N], g_qkvl[(size_t)MTOK * QKV_N];
__device__ __nv_bfloat16 g_xh[(size_t)MTOK * DIM],  g_xl[(size_t)MTOK * DIM];
__device__ __nv_bfloat16 g_wqh[(size_t)QKV_N * DIM], g_wql[(size_t)QKV_N * DIM];
__device__ __nv_bfloat16 g_wph[(size_t)INNER * DIM], g_wpl[(size_t)INNER * DIM];
__device__ __nv_bfloat16 g_ah[(size_t)MTOK * INNER], g_al[(size_t)MTOK * INNER];

// ---------------------------------------------------------------------------
// PTX helpers (baseline ISA only — plain sm_103 target)
// ---------------------------------------------------------------------------
__device__ __forceinline__ uint32_t smem_to_u32(const void* p) {
    uint32_t a;
    asm("{ .reg .u64 t; cvta.to.shared.u64 t, %1; cvt.u32.u64 %0, t; }"
        : "=r"(a) : "l"(p));
    return a;
}
__device__ __forceinline__ void cp_async16(uint32_t dst, const void* src) {
    asm volatile("cp.async.cg.shared.global [%0], [%1], 16;" :: "r"(dst), "l"(src));
}
#define CP_COMMIT() asm volatile("cp.async.commit_group;" ::: "memory")
#define CP_WAIT(n)  asm volatile("cp.async.wait_group %0;" :: "n"(n) : "memory")

#define LDSM_X4(r0, r1, r2, r3, addr) \
    asm volatile("ldmatrix.sync.aligned.m8n8.x4.shared.b16 {%0,%1,%2,%3}, [%4];" \
        : "=r"(r0), "=r"(r1), "=r"(r2), "=r"(r3) : "r"(addr))
#define LDSM_X4_T(r0, r1, r2, r3, addr) \
    asm volatile("ldmatrix.sync.aligned.m8n8.x4.trans.shared.b16 {%0,%1,%2,%3}, [%4];" \
        : "=r"(r0), "=r"(r1), "=r"(r2), "=r"(r3) : "r"(addr))

__device__ __forceinline__ void mma_bf16(float* c, const uint32_t* a, const uint32_t* b)
{
    asm volatile(
        "mma.sync.aligned.m16n8k16.row.col.f32.bf16.bf16.f32 "
        "{%0,%1,%2,%3}, {%4,%5,%6,%7}, {%8,%9}, {%0,%1,%2,%3};"
        : "+f"(c[0]), "+f"(c[1]), "+f"(c[2]), "+f"(c[3])
        : "r"(a[0]), "r"(a[1]), "r"(a[2]), "r"(a[3]), "r"(b[0]), "r"(b[1]));
}

__device__ __forceinline__ uint32_t pack2(__nv_bfloat16 a, __nv_bfloat16 b) {
    __nv_bfloat162 t(a, b);                 // x=a (lo half), y=b (hi half)
    return *reinterpret_cast<uint32_t*>(&t);
}
__device__ __forceinline__ uint32_t packf2(float lo, float hi) {
    __nv_bfloat162 t = __floats2bfloat162_rn(lo, hi);
    return *reinterpret_cast<uint32_t*>(&t);
}

// ---------------------------------------------------------------------------
// Split fp32 -> (hi bf16, lo bf16)
// ---------------------------------------------------------------------------
__global__ void split_kernel(const float* __restrict__ src,
                             __nv_bfloat16* __restrict__ hi,
                             __nv_bfloat16* __restrict__ lo, int n4)
{
    int i = blockIdx.x * 256 + threadIdx.x;
    if (i >= n4) return;
    float4 v = ((const float4*)src)[i];
    float f[4] = {v.x, v.y, v.z, v.w};
    __nv_bfloat162 h2[2], l2[2];
#pragma unroll
    for (int j = 0; j < 2; j++) {
        __nv_bfloat16 h0 = __float2bfloat16(f[2 * j]);
        __nv_bfloat16 h1 = __float2bfloat16(f[2 * j + 1]);
        __nv_bfloat16 l0 = __float2bfloat16(f[2 * j] - __bfloat162float(h0));
        __nv_bfloat16 l1 = __float2bfloat16(f[2 * j + 1] - __bfloat162float(h1));
        h2[j] = __nv_bfloat162(h0, h1);
        l2[j] = __nv_bfloat162(l0, l1);
    }
    ((__nv_bfloat162*)hi)[2 * i]     = h2[0];
    ((__nv_bfloat162*)hi)[2 * i + 1] = h2[1];
    ((__nv_bfloat162*)lo)[2 * i]     = l2[0];
    ((__nv_bfloat162*)lo)[2 * i + 1] = l2[1];
}

// ---------------------------------------------------------------------------
// Fused RoPE + hi/lo split: fp32 qkv -> bf16 qkvh/qkvl (rope on q,k only)
// idx = ((sec*2 + b)*2048 + t)*16*64 + h*64 + i ; sec in {0,1,2}
// ---------------------------------------------------------------------------
__global__ void rope_split_kernel(const float* __restrict__ qkv,
                                  __nv_bfloat16* __restrict__ qh,
                                  __nv_bfloat16* __restrict__ ql)
{
    int idx = blockIdx.x * 256 + threadIdx.x;
    int i   = idx & 63;
    int h   = (idx >> 6) & 15;
    int t   = (idx >> 10) & 2047;
    int b   = (idx >> 21) & 1;
    int sec = idx >> 22;             // 0=q,1=k,2=v

    size_t base = (size_t)(b * T_ + t) * QKV_N + sec * INNER + h * HEAD_DIM + i;
    float x1 = qkv[base];
    float x2 = qkv[base + 64];
    float y1 = x1, y2 = x2;
    if (sec < 2) {
        float inv = exp2f(-(float)i * 0.20761871929656223f);  // log2(1e4)/64
        float ang = (float)t * inv;
        float sn, cs;
        sincosf(ang, &sn, &cs);
        y1 = x1 * cs - x2 * sn;
        y2 = x2 * cs + x1 * sn;
    }
    __nv_bfloat16 h1 = __float2bfloat16(y1);
    __nv_bfloat16 h2 = __float2bfloat16(y2);
    qh[base]      = h1;
    qh[base + 64] = h2;
    ql[base]      = __float2bfloat16(y1 - __bfloat162float(h1));
    ql[base + 64] = __float2bfloat16(y2 - __bfloat162float(h2));
}

// ---------------------------------------------------------------------------
// HMMA GEMM (unchanged from round 3): C = (Ah+Al) @ (Bh+Bl)^T, 3-term split.
// ---------------------------------------------------------------------------
#define GBM 128
#define GBN 128
#define GBK 32
#define LDA 40
#define MAT_BYTES (128 * LDA * 2)
#define STAGE_BYTES (4 * MAT_BYTES)
#define GEMM_SMEM (2 * STAGE_BYTES)

__device__ __forceinline__ void issue_stage(
    const __nv_bfloat16* __restrict__ Ah, const __nv_bfloat16* __restrict__ Al,
    const __nv_bfloat16* __restrict__ Bh, const __nv_bfloat16* __restrict__ Bl,
    size_t bm, size_t bn, int K, int k0, uint32_t sbase, int tid)
{
#pragma unroll
    for (int i = 0; i < 2; i++) {
        int idx = tid + i * 256;
        int r   = idx >> 2;
        int c   = (idx & 3) << 3;
        uint32_t doff = (uint32_t)(r * LDA + c) * 2;
        size_t asrc = (bm + (size_t)r) * K + k0 + c;
        size_t bsrc = (bn + (size_t)r) * K + k0 + c;
        cp_async16(sbase + doff,                 Ah + asrc);
        cp_async16(sbase + MAT_BYTES + doff,     Al + asrc);
        cp_async16(sbase + 2 * MAT_BYTES + doff, Bh + bsrc);
        cp_async16(sbase + 3 * MAT_BYTES + doff, Bl + bsrc);
    }
}

__global__ __launch_bounds__(256, 1)
void gemm_bf16x3(const __nv_bfloat16* __restrict__ Ah, const __nv_bfloat16* __restrict__ Al,
                 const __nv_bfloat16* __restrict__ Bh, const __nv_bfloat16* __restrict__ Bl,
                 float* __restrict__ C, int M, int N, int K)
{
    extern __shared__ char smem[];
    const uint32_t s0 = smem_to_u32(smem);

    const int tid = threadIdx.x;
    const int wid = tid >> 5;
    const int l   = tid & 31;
    const int warp_m = wid & 1;
    const int warp_n = wid >> 1;
    const size_t bm = (size_t)blockIdx.y * GBM;
    const size_t bn = (size_t)blockIdx.x * GBN;

    float acc[4][4][4];
#pragma unroll
    for (int mi = 0; mi < 4; mi++)
#pragma unroll
        for (int ni = 0; ni < 4; ni++)
#pragma unroll
            for (int e = 0; e < 4; e++) acc[mi][ni][e] = 0.f;

    const int S = K / GBK;
    issue_stage(Ah, Al, Bh, Bl, bm, bn, K, 0, s0, tid);
    CP_COMMIT();

    const int a_row = warp_m * 64 + (l & 15);
    const int a_ch  = (l >> 4) * 8;
    const int g     = l >> 3;
    const int b_row = warp_n * 32 + ((g >> 1) << 3) + (l & 7);
    const int b_ch  = (g & 1) << 3;

    for (int s = 0; s < S; s++) {
        if (s + 1 < S) {
            issue_stage(Ah, Al, Bh, Bl, bm, bn, K, (s + 1) * GBK,
                        s0 + ((s + 1) & 1) * STAGE_BYTES, tid);
            CP_COMMIT();
            CP_WAIT(1);
        } else {
            CP_WAIT(0);
        }
        __syncthreads();

        const uint32_t ahB = s0 + (s & 1) * STAGE_BYTES;
        const uint32_t alB = ahB + MAT_BYTES;
        const uint32_t bhB = ahB + 2 * MAT_BYTES;
        const uint32_t blB = ahB + 3 * MAT_BYTES;

#pragma unroll
        for (int ks = 0; ks < 2; ks++) {
            const int kc = ks * 16;
            uint32_t ah[4][4], al[4][4], bh[4][2], bl[4][2];
#pragma unroll
            for (int mi = 0; mi < 4; mi++) {
                uint32_t off = (uint32_t)((a_row + mi * 16) * LDA + kc + a_ch) * 2;
                LDSM_X4(ah[mi][0], ah[mi][1], ah[mi][2], ah[mi][3], ahB + off);
                LDSM_X4(al[mi][0], al[mi][1], al[mi][2], al[mi][3], alB + off);
            }
#pragma unroll
            for (int nt = 0; nt < 2; nt++) {
                uint32_t off = (uint32_t)((b_row + nt * 16) * LDA + kc + b_ch) * 2;
                LDSM_X4(bh[2 * nt][0], bh[2 * nt][1], bh[2 * nt + 1][0], bh[2 * nt + 1][1], bhB + off);
                LDSM_X4(bl[2 * nt][0], bl[2 * nt][1], bl[2 * nt + 1][0], bl[2 * nt + 1][1], blB + off);
            }
#pragma unroll
            for (int mi = 0; mi < 4; mi++)
#pragma unroll
                for (int ni = 0; ni < 4; ni++)
                    mma_bf16(acc[mi][ni], ah[mi], bh[ni]);
#pragma unroll
            for (int mi = 0; mi < 4; mi++)
#pragma unroll
                for (int ni = 0; ni < 4; ni++)
                    mma_bf16(acc[mi][ni], al[mi], bh[ni]);
#pragma unroll
            for (int mi = 0; mi < 4; mi++)
#pragma unroll
                for (int ni = 0; ni < 4; ni++)
                    mma_bf16(acc[mi][ni], ah[mi], bl[ni]);
        }
        __syncthreads();
    }

    const size_t row0 = bm + warp_m * 64 + (l >> 2);
    const int    col0 = (int)bn + warp_n * 32 + 2 * (l & 3);
#pragma unroll
    for (int mi = 0; mi < 4; mi++) {
#pragma unroll
        for (int ni = 0; ni < 4; ni++) {
            float* p0 = C + (row0 + mi * 16) * N + col0 + ni * 8;
            float* p1 = p0 + 8 * (size_t)N;
            *(float2*)p0 = make_float2(acc[mi][ni][0], acc[mi][ni][1]);
            *(float2*)p1 = make_float2(acc[mi][ni][2], acc[mi][ni][3]);
        }
    }
}

// ---------------------------------------------------------------------------
// HMMA causal flash attention with hi/lo splits.
// BQ=128 (8 warps, warp = 16 q-rows), BKV=64, D=128. Double-buffered KV.
// S = QhKh + QlKh + QhKl ; PV = PhVh + PlVh + PhVl. Epilogue writes bf16 hi/lo.
// ---------------------------------------------------------------------------
#define ALD 136
#define AQ_BYTES   (128 * ALD * 2)     // 34816 per Q matrix
#define AKV_BYTES  (64 * ALD * 2)      // 17408 per KV matrix
#define AKV_STAGE  (4 * AKV_BYTES)     // 69632
#define ATTN_SMEM  (2 * AQ_BYTES + 2 * AKV_STAGE)   // 208896

__global__ __launch_bounds__(256, 1)
void attn_mma(const __nv_bfloat16* __restrict__ QKVh,
              const __nv_bfloat16* __restrict__ QKVl,
              __nv_bfloat16* __restrict__ outh,
              __nv_bfloat16* __restrict__ outl)
{
    extern __shared__ char smem[];
    const uint32_t s0  = smem_to_u32(smem);
    const uint32_t qhB = s0;
    const uint32_t qlB = s0 + AQ_BYTES;
    const uint32_t kvB = s0 + 2 * AQ_BYTES;

    const int tid = threadIdx.x;
    const int wid = tid >> 5;
    const int l   = tid & 31;
    const int qb  = (int)gridDim.x - 1 - (int)blockIdx.x;   // big tiles first
    const int b   = (int)blockIdx.y >> 4;
    const int h   = (int)blockIdx.y & 15;
    const int q0  = qb * 128;
    const size_t rowbase = (size_t)b * T_;
    const float scale = 0.08838834764831843f;  // 1/sqrt(128)

    // ---- Q prologue: 2 mats x 128 rows x 16 chunks ----
#pragma unroll
    for (int it = 0; it < 16; it++) {
        int idx = tid + it * 256;               // 0..4095
        int mat = idx >> 11;                    // 0=hi,1=lo
        int r   = (idx >> 4) & 127;
        int c   = idx & 15;
        const __nv_bfloat16* src = (mat ? QKVl : QKVh) +
            (rowbase + q0 + r) * QKV_N + h * HEAD_DIM + c * 8;
        cp_async16((mat ? qlB : qhB) + (uint32_t)(r * ALD + c * 8) * 2, src);
    }

    // ---- KV stage issue ----
    auto issue_kv = [&](int kv0, int buf) {
        uint32_t base = kvB + (uint32_t)buf * AKV_STAGE;
#pragma unroll
        for (int it = 0; it < 16; it++) {
            int idx = tid + it * 256;           // 0..4095
            int m   = idx >> 10;                // 0=Kh 1=Kl 2=Vh 3=Vl
            int r   = (idx >> 4) & 63;
            int c   = idx & 15;
            const __nv_bfloat16* p = (m & 1) ? QKVl : QKVh;
            int sect = (m >> 1) ? 2 * INNER : INNER;
            const __nv_bfloat16* src = p +
                (rowbase + kv0 + r) * QKV_N + sect + h * HEAD_DIM + c * 8;
            cp_async16(base + (uint32_t)m * AKV_BYTES + (uint32_t)(r * ALD + c * 8) * 2, src);
        }
    };

    // lane mappings
    const int a_row  = wid * 16 + (l & 15);
    const int a_ch   = (l >> 4) << 3;
    const int g      = l >> 3;
    const int bn_row = ((g >> 1) << 3) + (l & 7);
    const int b_ch   = (g & 1) << 3;
    const int v_kr   = (((l >> 3) & 1) << 3) + (l & 7);
    const int v_nc   = (l >> 4) << 3;

    float o[16][4];
#pragma unroll
    for (int n = 0; n < 16; n++)
#pragma unroll
        for (int e = 0; e < 4; e++) o[n][e] = 0.f;
    float mA = -INFINITY, mB = -INFINITY, lA = 0.f, lB = 0.f;

    const int ntiles = 2 * qb + 2;
    issue_kv(0, 0);
    CP_COMMIT();

    const int row0 = q0 + wid * 16;
    const int r0l  = l >> 2;
    const int rowA = row0 + r0l;
    const int rowB = rowA + 8;

    for (int t = 0; t < ntiles; t++) {
        if (t + 1 < ntiles) {
            issue_kv((t + 1) * 64, (t + 1) & 1);
            CP_COMMIT();
            CP_WAIT(1);
        } else {
            CP_WAIT(0);
        }
        __syncthreads();

        const int kv0 = t * 64;
        const uint32_t st = kvB + (uint32_t)(t & 1) * AKV_STAGE;

        if (kv0 <= row0 + 15) {                    // warp has unmasked rows
            // ---- S = Q K^T (3-term split) ----
            float s[8][4];
#pragma unroll
            for (int n = 0; n < 8; n++)
#pragma unroll
                for (int e = 0; e < 4; e++) s[n][e] = 0.f;

#pragma unroll
            for (int kk = 0; kk < 8; kk++) {
                const int kc = kk * 16;
                uint32_t qa[4], qla[4], kh[8][2], kl[8][2];
                uint32_t qoff = (uint32_t)(a_row * ALD + kc + a_ch) * 2;
                LDSM_X4(qa[0], qa[1], qa[2], qa[3], qhB + qoff);
                LDSM_X4(qla[0], qla[1], qla[2], qla[3], qlB + qoff);
#pragma unroll
                for (int nt = 0; nt < 4; nt++) {
                    uint32_t koff = (uint32_t)((nt * 16 + bn_row) * ALD + kc + b_ch) * 2;
                    LDSM_X4(kh[2 * nt][0], kh[2 * nt][1], kh[2 * nt + 1][0], kh[2 * nt + 1][1],
                            st + koff);
                    LDSM_X4(kl[2 * nt][0], kl[2 * nt][1], kl[2 * nt + 1][0], kl[2 * nt + 1][1],
                            st + AKV_BYTES + koff);
                }
#pragma unroll
                for (int n = 0; n < 8; n++) {
                    mma_bf16(s[n], qa,  kh[n]);
                    mma_bf16(s[n], qla, kh[n]);
                    mma_bf16(s[n], qa,  kl[n]);
                }
            }

            // ---- scale + causal mask ----
#pragma unroll
            for (int n = 0; n < 8; n++)
#pragma unroll
                for (int e = 0; e < 4; e++) s[n][e] *= scale;

            if (kv0 + 63 > row0) {
                const int cb = kv0 + 2 * (l & 3);
#pragma unroll
                for (int n = 0; n < 8; n++) {
                    int c0 = cb + 8 * n;
                    if (c0     > rowA) s[n][0] = -INFINITY;
                    if (c0 + 1 > rowA) s[n][1] = -INFINITY;
                    if (c0     > rowB) s[n][2] = -INFINITY;
                    if (c0 + 1 > rowB) s[n][3] = -INFINITY;
                }
            }

            // ---- online softmax ----
            float mxA = -INFINITY, mxB = -INFINITY;
#pragma unroll
            for (int n = 0; n < 8; n++) {
                mxA = fmaxf(mxA, fmaxf(s[n][0], s[n][1]));
                mxB = fmaxf(mxB, fmaxf(s[n][2], s[n][3]));
            }
#pragma unroll
            for (int off = 1; off < 4; off <<= 1) {
                mxA = fmaxf(mxA, __shfl_xor_sync(0xffffffffu, mxA, off));
                mxB = fmaxf(mxB, __shfl_xor_sync(0xffffffffu, mxB, off));
            }
            float mnA = fmaxf(mA, mxA), mnB = fmaxf(mB, mxB);
            float cA = __expf(mA - mnA), cB = __expf(mB - mnB);
            float rsA = 0.f, rsB = 0.f;
#pragma unroll
            for (int n = 0; n < 8; n++) {
                s[n][0] = __expf(s[n][0] - mnA);
                s[n][1] = __expf(s[n][1] - mnA);
                s[n][2] = __expf(s[n][2] - mnB);
                s[n][3] = __expf(s[n][3] - mnB);
                rsA += s[n][0] + s[n][1];
                rsB += s[n][2] + s[n][3];
            }
#pragma unroll
            for (int off = 1; off < 4; off <<= 1) {
                rsA += __shfl_xor_sync(0xffffffffu, rsA, off);
                rsB += __shfl_xor_sync(0xffffffffu, rsB, off);
            }
            lA = lA * cA + rsA;  mA = mnA;
            lB = lB * cB + rsB;  mB = mnB;
#pragma unroll
            for (int n = 0; n < 16; n++) {
                o[n][0] *= cA; o[n][1] *= cA;
                o[n][2] *= cB; o[n][3] *= cB;
            }

            // ---- build P fragments (hi/lo) ----
            uint32_t ph[4][4], pl[4][4];
#pragma unroll
            for (int j2 = 0; j2 < 4; j2++) {
#pragma unroll
                for (int hf = 0; hf < 2; hf++) {
                    int j = 2 * j2 + hf;
                    __nv_bfloat16 h0 = __float2bfloat16(s[j][0]);
                    __nv_bfloat16 h1 = __float2bfloat16(s[j][1]);
                    __nv_bfloat16 h2 = __float2bfloat16(s[j][2]);
                    __nv_bfloat16 h3 = __float2bfloat16(s[j][3]);
                    ph[j2][2 * hf]     = pack2(h0, h1);
                    ph[j2][2 * hf + 1] = pack2(h2, h3);
                    pl[j2][2 * hf]     = packf2(s[j][0] - __bfloat162float(h0),
                                                s[j][1] - __bfloat162float(h1));
                    pl[j2][2 * hf + 1] = packf2(s[j][2] - __bfloat162float(h2),
                                                s[j][3] - __bfloat162float(h3));
                }
            }

            // ---- O += P V (3-term split) ----
#pragma unroll
            for (int j2 = 0; j2 < 4; j2++) {
#pragma unroll
                for (int nn = 0; nn < 8; nn++) {
                    uint32_t voff = (uint32_t)((j2 * 16 + v_kr) * ALD + nn * 16 + v_nc) * 2;
                    uint32_t vh01[2], vh23[2], vl01[2], vl23[2];
                    LDSM_X4_T(vh01[0], vh01[1], vh23[0], vh23[1], st + 2 * AKV_BYTES + voff);
                    LDSM_X4_T(vl01[0], vl01[1], vl23[0], vl23[1], st + 3 * AKV_BYTES + voff);
                    mma_bf16(o[2 * nn],     ph[j2], vh01);
                    mma_bf16(o[2 * nn + 1], ph[j2], vh23);
                    mma_bf16(o[2 * nn],     pl[j2], vh01);
                    mma_bf16(o[2 * nn + 1], pl[j2], vh23);
                    mma_bf16(o[2 * nn],     ph[j2], vl01);
                    mma_bf16(o[2 * nn + 1], ph[j2], vl23);
                }
            }
        }
        __syncthreads();
    }

    // ---- epilogue: normalize, split to bf16 hi/lo, store ----
    const float iA = 1.f / lA;
    const float iB = 1.f / lB;
    const size_t bA = (rowbase + rowA) * (size_t)INNER + h * HEAD_DIM + 2 * (l & 3);
    const size_t bB = bA + 8 * (size_t)INNER;
#pragma unroll
    for (int n = 0; n < 16; n++) {
        float vA0 = o[n][0] * iA, vA1 = o[n][1] * iA;
        float vB0 = o[n][2] * iB, vB1 = o[n][3] * iB;
        __nv_bfloat16 hA0 = __float2bfloat16(vA0), hA1 = __float2bfloat16(vA1);
        __nv_bfloat16 hB0 = __float2bfloat16(vB0), hB1 = __float2bfloat16(vB1);
        *(uint32_t*)(outh + bA + 8 * n) = pack2(hA0, hA1);
        *(uint32_t*)(outh + bB + 8 * n) = pack2(hB0, hB1);
        *(uint32_t*)(outl + bA + 8 * n) = packf2(vA0 - __bfloat162float(hA0),
                                                 vA1 - __bfloat162float(hA1));
        *(uint32_t*)(outl + bB + 8 * n) = packf2(vB0 - __bfloat162float(hB0),
                                                 vB1 - __bfloat162float(hB1));
    }
}

// ---------------------------------------------------------------------------
extern "C" void kernel_launch(void* const* d_in, const int* in_sizes, int n_in,
                              void* d_out, int out_size)
{
    const float* x      = (const float*)d_in[0];   // [2,2048,2048]
    const float* W_qkv  = (const float*)d_in[1];   // [6144,2048]
    const float* W_proj = (const float*)d_in[2];   // [2048,2048]
    float* out = (float*)d_out;                    // [2,2048,2048]

    float *qkv_ptr;
    __nv_bfloat16 *qkvh, *qkvl, *xh, *xl, *wqh, *wql, *wph, *wpl, *ah, *al;
    cudaGetSymbolAddress((void**)&qkv_ptr, g_qkv);
    cudaGetSymbolAddress((void**)&qkvh, g_qkvh);
    cudaGetSymbolAddress((void**)&qkvl, g_qkvl);
    cudaGetSymbolAddress((void**)&xh, g_xh);
    cudaGetSymbolAddress((void**)&xl, g_xl);
    cudaGetSymbolAddress((void**)&wqh, g_wqh);
    cudaGetSymbolAddress((void**)&wql, g_wql);
    cudaGetSymbolAddress((void**)&wph, g_wph);
    cudaGetSymbolAddress((void**)&wpl, g_wpl);
    cudaGetSymbolAddress((void**)&ah, g_ah);
    cudaGetSymbolAddress((void**)&al, g_al);

    cudaFuncSetAttribute(gemm_bf16x3, cudaFuncAttributeMaxDynamicSharedMemorySize,
                         GEMM_SMEM);
    cudaFuncSetAttribute(attn_mma, cudaFuncAttributeMaxDynamicSharedMemorySize,
                         ATTN_SMEM);

    // Split inputs/weights into bf16 hi/lo
    split_kernel<<<(MTOK * DIM / 4) / 256, 256>>>(x, xh, xl, MTOK * DIM / 4);
    split_kernel<<<(QKV_N * DIM / 4) / 256, 256>>>(W_qkv, wqh, wql, QKV_N * DIM / 4);
    split_kernel<<<(INNER * DIM / 4) / 256, 256>>>(W_proj, wph, wpl, INNER * DIM / 4);

    // 1) qkv = x @ W_qkv^T (HMMA)
    gemm_bf16x3<<<dim3(QKV_N / GBN, MTOK / GBM), 256, GEMM_SMEM>>>(
        xh, xl, wqh, wql, qkv_ptr, MTOK, QKV_N, DIM);

    // 2) fused RoPE + split -> bf16 hi/lo qkv
    rope_split_kernel<<<(3 * B_ * T_ * HEADS * 64) / 256, 256>>>(qkv_ptr, qkvh, qkvl);

    // 3) HMMA causal flash attention -> bf16 hi/lo proj input
    attn_mma<<<dim3(T_ / 128, B_ * HEADS), 256, ATTN_SMEM>>>(qkvh, qkvl, ah, al);

    // 4) out = attn @ W_proj^T (HMMA)
    gemm_bf16x3<<<dim3(INNER / GBN, MTOK / GBM), 256, GEMM_SMEM>>>(
        ah, al, wph, wpl, out, MTOK, INNER, DIM);
}

// round 5
// speedup vs baseline: 3.2172x; 1.0584x over previous
#include <cuda_runtime.h>
#include <cuda_bf16.h>
#include <math.h>
#include <cstdint>

#define HEADS    16
#define HEAD_DIM 128
#define B_       2
#define T_       2048
#define DIM      2048
#define INNER    (HEADS * HEAD_DIM)   // 2048
#define QKV_N    (3 * INNER)          // 6144
#define MTOK     (B_ * T_)            // 4096

// ---------------------------------------------------------------------------
// Scratch (allocation-free rule: __device__ globals)
// ---------------------------------------------------------------------------
__device__ float g_qkv[(size_t)MTOK * QKV_N];    // fp32 qkv (pre-rope)
__device__ __nv_bfloat16 g_qkvh[(size_t)MTOK * QKV_N], g_qkvl[(size_t)MTOK * QKV_N];
__device__ __nv_bfloat16 g_xh[(size_t)MTOK * DIM],  g_xl[(size_t)MTOK * DIM];
__device__ __nv_bfloat16 g_wqh[(size_t)QKV_N * DIM], g_wql[(size_t)QKV_N * DIM];
__device__ __nv_bfloat16 g_wph[(size_t)INNER * DIM], g_wpl[(size_t)INNER * DIM];
__device__ __nv_bfloat16 g_ah[(size_t)MTOK * INNER], g_al[(size_t)MTOK * INNER];

// ---------------------------------------------------------------------------
// PTX helpers (baseline ISA only — plain sm_103 target)
// ---------------------------------------------------------------------------
__device__ __forceinline__ uint32_t smem_to_u32(const void* p) {
    uint32_t a;
    asm("{ .reg .u64 t; cvta.to.shared.u64 t, %1; cvt.u32.u64 %0, t; }"
        : "=r"(a) : "l"(p));
    return a;
}
__device__ __forceinline__ void cp_async16(uint32_t dst, const void* src) {
    asm volatile("cp.async.cg.shared.global [%0], [%1], 16;" :: "r"(dst), "l"(src));
}
#define CP_COMMIT() asm volatile("cp.async.commit_group;" ::: "memory")
#define CP_WAIT(n)  asm volatile("cp.async.wait_group %0;" :: "n"(n) : "memory")

#define LDSM_X4(r0, r1, r2, r3, addr) \
    asm volatile("ldmatrix.sync.aligned.m8n8.x4.shared.b16 {%0,%1,%2,%3}, [%4];" \
        : "=r"(r0), "=r"(r1), "=r"(r2), "=r"(r3) : "r"(addr))
#define LDSM_X4_T(r0, r1, r2, r3, addr) \
    asm volatile("ldmatrix.sync.aligned.m8n8.x4.trans.shared.b16 {%0,%1,%2,%3}, [%4];" \
        : "=r"(r0), "=r"(r1), "=r"(r2), "=r"(r3) : "r"(addr))

__device__ __forceinline__ void mma_bf16(float* c, const uint32_t* a, const uint32_t* b)
{
    asm volatile(
        "mma.sync.aligned.m16n8k16.row.col.f32.bf16.bf16.f32 "
        "{%0,%1,%2,%3}, {%4,%5,%6,%7}, {%8,%9}, {%0,%1,%2,%3};"
        : "+f"(c[0]), "+f"(c[1]), "+f"(c[2]), "+f"(c[3])
        : "r"(a[0]), "r"(a[1]), "r"(a[2]), "r"(a[3]), "r"(b[0]), "r"(b[1]));
}

__device__ __forceinline__ uint32_t pack2(__nv_bfloat16 a, __nv_bfloat16 b) {
    __nv_bfloat162 t(a, b);
    return *reinterpret_cast<uint32_t*>(&t);
}
__device__ __forceinline__ uint32_t packf2(float lo, float hi) {
    __nv_bfloat162 t = __floats2bfloat162_rn(lo, hi);
    return *reinterpret_cast<uint32_t*>(&t);
}

// ---------------------------------------------------------------------------
// Split fp32 -> (hi bf16, lo bf16)
// ---------------------------------------------------------------------------
__global__ void split_kernel(const float* __restrict__ src,
                             __nv_bfloat16* __restrict__ hi,
                             __nv_bfloat16* __restrict__ lo, int n4)
{
    int i = blockIdx.x * 256 + threadIdx.x;
    if (i >= n4) return;
    float4 v = ((const float4*)src)[i];
    float f[4] = {v.x, v.y, v.z, v.w};
    __nv_bfloat162 h2[2], l2[2];
#pragma unroll
    for (int j = 0; j < 2; j++) {
        __nv_bfloat16 h0 = __float2bfloat16(f[2 * j]);
        __nv_bfloat16 h1 = __float2bfloat16(f[2 * j + 1]);
        __nv_bfloat16 l0 = __float2bfloat16(f[2 * j] - __bfloat162float(h0));
        __nv_bfloat16 l1 = __float2bfloat16(f[2 * j + 1] - __bfloat162float(h1));
        h2[j] = __nv_bfloat162(h0, h1);
        l2[j] = __nv_bfloat162(l0, l1);
    }
    ((__nv_bfloat162*)hi)[2 * i]     = h2[0];
    ((__nv_bfloat162*)hi)[2 * i + 1] = h2[1];
    ((__nv_bfloat162*)lo)[2 * i]     = l2[0];
    ((__nv_bfloat162*)lo)[2 * i + 1] = l2[1];
}

// ---------------------------------------------------------------------------
// Fused RoPE + hi/lo split
// ---------------------------------------------------------------------------
__global__ void rope_split_kernel(const float* __restrict__ qkv,
                                  __nv_bfloat16* __restrict__ qh,
                                  __nv_bfloat16* __restrict__ ql)
{
    int idx = blockIdx.x * 256 + threadIdx.x;
    int i   = idx & 63;
    int h   = (idx >> 6) & 15;
    int t   = (idx >> 10) & 2047;
    int b   = (idx >> 21) & 1;
    int sec = idx >> 22;             // 0=q,1=k,2=v

    size_t base = (size_t)(b * T_ + t) * QKV_N + sec * INNER + h * HEAD_DIM + i;
    float x1 = qkv[base];
    float x2 = qkv[base + 64];
    float y1 = x1, y2 = x2;
    if (sec < 2) {
        float inv = exp2f(-(float)i * 0.20761871929656223f);  // log2(1e4)/64
        float ang = (float)t * inv;
        float sn, cs;
        sincosf(ang, &sn, &cs);
        y1 = x1 * cs - x2 * sn;
        y2 = x2 * cs + x1 * sn;
    }
    __nv_bfloat16 h1 = __float2bfloat16(y1);
    __nv_bfloat16 h2 = __float2bfloat16(y2);
    qh[base]      = h1;
    qh[base + 64] = h2;
    ql[base]      = __float2bfloat16(y1 - __bfloat162float(h1));
    ql[base + 64] = __float2bfloat16(y2 - __bfloat162float(h2));
}

// ---------------------------------------------------------------------------
// HMMA GEMM v2: C[M,N](fp32) = (Ah+Al) @ (Bh+Bl)^T, 3-term bf16 split.
// Tile 128x256, BK=32, 8 warps (2x4), warp tile 64x64.
// 3-stage cp.async pipeline (61.4KB/stage).
// ---------------------------------------------------------------------------
#define GBM 128
#define GBN 256
#define GBK 32
#define LDA 40
#define A_BYTES (128 * LDA * 2)          // 10240 per A matrix
#define B_BYTES (256 * LDA * 2)          // 20480 per B matrix
#define STAGE_BYTES (2 * A_BYTES + 2 * B_BYTES)   // 61440
#define GEMM_SMEM (3 * STAGE_BYTES)               // 184320

__device__ __forceinline__ void issue_stage(
    const __nv_bfloat16* __restrict__ Ah, const __nv_bfloat16* __restrict__ Al,
    const __nv_bfloat16* __restrict__ Bh, const __nv_bfloat16* __restrict__ Bl,
    size_t bm, size_t bn, int K, int k0, uint32_t sbase, int tid)
{
    // A: 128 rows x 4 chunks x 2 mats = 1024 cp16
#pragma unroll
    for (int i = 0; i < 4; i++) {
        int idx = tid + i * 256;             // 0..1023
        int mat = idx >> 9;                  // 0=hi,1=lo
        int r   = (idx >> 2) & 127;
        int c   = (idx & 3) << 3;
        const __nv_bfloat16* src = (mat ? Al : Ah) + (bm + (size_t)r) * K + k0 + c;
        cp_async16(sbase + (uint32_t)mat * A_BYTES + (uint32_t)(r * LDA + c) * 2, src);
    }
    // B: 256 rows x 4 chunks x 2 mats = 2048 cp16
#pragma unroll
    for (int i = 0; i < 8; i++) {
        int idx = tid + i * 256;             // 0..2047
        int mat = idx >> 10;
        int r   = (idx >> 2) & 255;
        int c   = (idx & 3) << 3;
        const __nv_bfloat16* src = (mat ? Bl : Bh) + (bn + (size_t)r) * K + k0 + c;
        cp_async16(sbase + 2 * A_BYTES + (uint32_t)mat * B_BYTES +
                   (uint32_t)(r * LDA + c) * 2, src);
    }
}

__global__ __launch_bounds__(256, 1)
void gemm_bf16x3(const __nv_bfloat16* __restrict__ Ah, const __nv_bfloat16* __restrict__ Al,
                 const __nv_bfloat16* __restrict__ Bh, const __nv_bfloat16* __restrict__ Bl,
                 float* __restrict__ C, int M, int N, int K)
{
    extern __shared__ char smem[];
    const uint32_t s0 = smem_to_u32(smem);

    const int tid = threadIdx.x;
    const int wid = tid >> 5;
    const int l   = tid & 31;
    const int warp_m = wid & 1;              // 2 in M -> 64 rows
    const int warp_n = wid >> 1;             // 4 in N -> 64 cols
    const size_t bm = (size_t)blockIdx.y * GBM;
    const size_t bn = (size_t)blockIdx.x * GBN;

    float acc[4][8][4];
#pragma unroll
    for (int mi = 0; mi < 4; mi++)
#pragma unroll
        for (int ni = 0; ni < 8; ni++)
#pragma unroll
            for (int e = 0; e < 4; e++) acc[mi][ni][e] = 0.f;

    const int S = K / GBK;                   // 64
    issue_stage(Ah, Al, Bh, Bl, bm, bn, K, 0, s0, tid);
    CP_COMMIT();
    issue_stage(Ah, Al, Bh, Bl, bm, bn, K, GBK, s0 + STAGE_BYTES, tid);
    CP_COMMIT();

    const int a_row  = warp_m * 64 + (l & 15);
    const int a_ch   = (l >> 4) << 3;
    const int g      = l >> 3;
    const int b_rowl = ((g >> 1) << 3) + (l & 7);
    const int b_ch   = (g & 1) << 3;

    int buf = 0;
    for (int s = 0; s < S; s++) {
        if (s + 2 < S) {
            int nb = buf + 2; if (nb >= 3) nb -= 3;
            issue_stage(Ah, Al, Bh, Bl, bm, bn, K, (s + 2) * GBK,
                        s0 + (uint32_t)nb * STAGE_BYTES, tid);
            CP_COMMIT();
            CP_WAIT(2);
        } else if (s + 1 < S) {
            CP_WAIT(1);
        } else {
            CP_WAIT(0);
        }
        __syncthreads();

        const uint32_t ahB = s0 + (uint32_t)buf * STAGE_BYTES;
        const uint32_t alB = ahB + A_BYTES;
        const uint32_t bhB = ahB + 2 * A_BYTES;
        const uint32_t blB = bhB + B_BYTES;

#pragma unroll
        for (int ks = 0; ks < 2; ks++) {
            const int kc = ks * 16;
            uint32_t ah[4][4], al[4][4], bh[8][2], bl[8][2];
#pragma unroll
            for (int mi = 0; mi < 4; mi++) {
                uint32_t off = (uint32_t)((a_row + mi * 16) * LDA + kc + a_ch) * 2;
                LDSM_X4(ah[mi][0], ah[mi][1], ah[mi][2], ah[mi][3], ahB + off);
                LDSM_X4(al[mi][0], al[mi][1], al[mi][2], al[mi][3], alB + off);
            }
#pragma unroll
            for (int nt = 0; nt < 4; nt++) {
                uint32_t off = (uint32_t)((warp_n * 64 + nt * 16 + b_rowl) * LDA + kc + b_ch) * 2;
                LDSM_X4(bh[2 * nt][0], bh[2 * nt][1], bh[2 * nt + 1][0], bh[2 * nt + 1][1], bhB + off);
                LDSM_X4(bl[2 * nt][0], bl[2 * nt][1], bl[2 * nt + 1][0], bl[2 * nt + 1][1], blB + off);
            }
#pragma unroll
            for (int mi = 0; mi < 4; mi++)
#pragma unroll
                for (int ni = 0; ni < 8; ni++)
                    mma_bf16(acc[mi][ni], ah[mi], bh[ni]);
#pragma unroll
            for (int mi = 0; mi < 4; mi++)
#pragma unroll
                for (int ni = 0; ni < 8; ni++)
                    mma_bf16(acc[mi][ni], al[mi], bh[ni]);
#pragma unroll
            for (int mi = 0; mi < 4; mi++)
#pragma unroll
                for (int ni = 0; ni < 8; ni++)
                    mma_bf16(acc[mi][ni], ah[mi], bl[ni]);
        }
        __syncthreads();
        if (++buf == 3) buf = 0;
    }

    // Epilogue
    const size_t row0 = bm + warp_m * 64 + (l >> 2);
    const int    col0 = (int)bn + warp_n * 64 + 2 * (l & 3);
#pragma unroll
    for (int mi = 0; mi < 4; mi++) {
#pragma unroll
        for (int ni = 0; ni < 8; ni++) {
            float* p0 = C + (row0 + mi * 16) * N + col0 + ni * 8;
            float* p1 = p0 + 8 * (size_t)N;
            *(float2*)p0 = make_float2(acc[mi][ni][0], acc[mi][ni][1]);
            *(float2*)p1 = make_float2(acc[mi][ni][2], acc[mi][ni][3]);
        }
    }
}

// ---------------------------------------------------------------------------
// HMMA causal flash attention with hi/lo splits (unchanged from round 4).
// ---------------------------------------------------------------------------
#define ALD 136
#define AQ_BYTES   (128 * ALD * 2)
#define AKV_BYTES  (64 * ALD * 2)
#define AKV_STAGE  (4 * AKV_BYTES)
#define ATTN_SMEM  (2 * AQ_BYTES + 2 * AKV_STAGE)

__global__ __launch_bounds__(256, 1)
void attn_mma(const __nv_bfloat16* __restrict__ QKVh,
              const __nv_bfloat16* __restrict__ QKVl,
              __nv_bfloat16* __restrict__ outh,
              __nv_bfloat16* __restrict__ outl)
{
    extern __shared__ char smem[];
    const uint32_t s0  = smem_to_u32(smem);
    const uint32_t qhB = s0;
    const uint32_t qlB = s0 + AQ_BYTES;
    const uint32_t kvB = s0 + 2 * AQ_BYTES;

    const int tid = threadIdx.x;
    const int wid = tid >> 5;
    const int l   = tid & 31;
    const int qb  = (int)gridDim.x - 1 - (int)blockIdx.x;
    const int b   = (int)blockIdx.y >> 4;
    const int h   = (int)blockIdx.y & 15;
    const int q0  = qb * 128;
    const size_t rowbase = (size_t)b * T_;
    const float scale = 0.08838834764831843f;

#pragma unroll
    for (int it = 0; it < 16; it++) {
        int idx = tid + it * 256;
        int mat = idx >> 11;
        int r   = (idx >> 4) & 127;
        int c   = idx & 15;
        const __nv_bfloat16* src = (mat ? QKVl : QKVh) +
            (rowbase + q0 + r) * QKV_N + h * HEAD_DIM + c * 8;
        cp_async16((mat ? qlB : qhB) + (uint32_t)(r * ALD + c * 8) * 2, src);
    }

    auto issue_kv = [&](int kv0, int buf) {
        uint32_t base = kvB + (uint32_t)buf * AKV_STAGE;
#pragma unroll
        for (int it = 0; it < 16; it++) {
            int idx = tid + it * 256;
            int m   = idx >> 10;
            int r   = (idx >> 4) & 63;
            int c   = idx & 15;
            const __nv_bfloat16* p = (m & 1) ? QKVl : QKVh;
            int sect = (m >> 1) ? 2 * INNER : INNER;
            const __nv_bfloat16* src = p +
                (rowbase + kv0 + r) * QKV_N + sect + h * HEAD_DIM + c * 8;
            cp_async16(base + (uint32_t)m * AKV_BYTES + (uint32_t)(r * ALD + c * 8) * 2, src);
        }
    };

    const int a_row  = wid * 16 + (l & 15);
    const int a_ch   = (l >> 4) << 3;
    const int g      = l >> 3;
    const int bn_row = ((g >> 1) << 3) + (l & 7);
    const int b_ch   = (g & 1) << 3;
    const int v_kr   = (((l >> 3) & 1) << 3) + (l & 7);
    const int v_nc   = (l >> 4) << 3;

    float o[16][4];
#pragma unroll
    for (int n = 0; n < 16; n++)
#pragma unroll
        for (int e = 0; e < 4; e++) o[n][e] = 0.f;
    float mA = -INFINITY, mB = -INFINITY, lA = 0.f, lB = 0.f;

    const int ntiles = 2 * qb + 2;
    issue_kv(0, 0);
    CP_COMMIT();

    const int row0 = q0 + wid * 16;
    const int r0l  = l >> 2;
    const int rowA = row0 + r0l;
    const int rowB = rowA + 8;

    for (int t = 0; t < ntiles; t++) {
        if (t + 1 < ntiles) {
            issue_kv((t + 1) * 64, (t + 1) & 1);
            CP_COMMIT();
            CP_WAIT(1);
        } else {
            CP_WAIT(0);
        }
        __syncthreads();

        const int kv0 = t * 64;
        const uint32_t st = kvB + (uint32_t)(t & 1) * AKV_STAGE;

        if (kv0 <= row0 + 15) {
            float s[8][4];
#pragma unroll
            for (int n = 0; n < 8; n++)
#pragma unroll
                for (int e = 0; e < 4; e++) s[n][e] = 0.f;

#pragma unroll
            for (int kk = 0; kk < 8; kk++) {
                const int kc = kk * 16;
                uint32_t qa[4], qla[4], kh[8][2], kl[8][2];
                uint32_t qoff = (uint32_t)(a_row * ALD + kc + a_ch) * 2;
                LDSM_X4(qa[0], qa[1], qa[2], qa[3], qhB + qoff);
                LDSM_X4(qla[0], qla[1], qla[2], qla[3], qlB + qoff);
#pragma unroll
                for (int nt = 0; nt < 4; nt++) {
                    uint32_t koff = (uint32_t)((nt * 16 + bn_row) * ALD + kc + b_ch) * 2;
                    LDSM_X4(kh[2 * nt][0], kh[2 * nt][1], kh[2 * nt + 1][0], kh[2 * nt + 1][1],
                            st + koff);
                    LDSM_X4(kl[2 * nt][0], kl[2 * nt][1], kl[2 * nt + 1][0], kl[2 * nt + 1][1],
                            st + AKV_BYTES + koff);
                }
#pragma unroll
                for (int n = 0; n < 8; n++) {
                    mma_bf16(s[n], qa,  kh[n]);
                    mma_bf16(s[n], qla, kh[n]);
                    mma_bf16(s[n], qa,  kl[n]);
                }
            }

#pragma unroll
            for (int n = 0; n < 8; n++)
#pragma unroll
                for (int e = 0; e < 4; e++) s[n][e] *= scale;

            if (kv0 + 63 > row0) {
                const int cb = kv0 + 2 * (l & 3);
#pragma unroll
                for (int n = 0; n < 8; n++) {
                    int c0 = cb + 8 * n;
                    if (c0     > rowA) s[n][0] = -INFINITY;
                    if (c0 + 1 > rowA) s[n][1] = -INFINITY;
                    if (c0     > rowB) s[n][2] = -INFINITY;
                    if (c0 + 1 > rowB) s[n][3] = -INFINITY;
                }
            }

            float mxA = -INFINITY, mxB = -INFINITY;
#pragma unroll
            for (int n = 0; n < 8; n++) {
                mxA = fmaxf(mxA, fmaxf(s[n][0], s[n][1]));
                mxB = fmaxf(mxB, fmaxf(s[n][2], s[n][3]));
            }
#pragma unroll
            for (int off = 1; off < 4; off <<= 1) {
                mxA = fmaxf(mxA, __shfl_xor_sync(0xffffffffu, mxA, off));
                mxB = fmaxf(mxB, __shfl_xor_sync(0xffffffffu, mxB, off));
            }
            float mnA = fmaxf(mA, mxA), mnB = fmaxf(mB, mxB);
            float cA = __expf(mA - mnA), cB = __expf(mB - mnB);
            float rsA = 0.f, rsB = 0.f;
#pragma unroll
            for (int n = 0; n < 8; n++) {
                s[n][0] = __expf(s[n][0] - mnA);
                s[n][1] = __expf(s[n][1] - mnA);
                s[n][2] = __expf(s[n][2] - mnB);
                s[n][3] = __expf(s[n][3] - mnB);
                rsA += s[n][0] + s[n][1];
                rsB += s[n][2] + s[n][3];
            }
#pragma unroll
            for (int off = 1; off < 4; off <<= 1) {
                rsA += __shfl_xor_sync(0xffffffffu, rsA, off);
                rsB += __shfl_xor_sync(0xffffffffu, rsB, off);
            }
            lA = lA * cA + rsA;  mA = mnA;
            lB = lB * cB + rsB;  mB = mnB;
#pragma unroll
            for (int n = 0; n < 16; n++) {
                o[n][0] *= cA; o[n][1] *= cA;
                o[n][2] *= cB; o[n][3] *= cB;
            }

            uint32_t ph[4][4], pl[4][4];
#pragma unroll
            for (int j2 = 0; j2 < 4; j2++) {
#pragma unroll
                for (int hf = 0; hf < 2; hf++) {
                    int j = 2 * j2 + hf;
                    __nv_bfloat16 h0 = __float2bfloat16(s[j][0]);
                    __nv_bfloat16 h1 = __float2bfloat16(s[j][1]);
                    __nv_bfloat16 h2 = __float2bfloat16(s[j][2]);
                    __nv_bfloat16 h3 = __float2bfloat16(s[j][3]);
                    ph[j2][2 * hf]     = pack2(h0, h1);
                    ph[j2][2 * hf + 1] = pack2(h2, h3);
                    pl[j2][2 * hf]     = packf2(s[j][0] - __bfloat162float(h0),
                                                s[j][1] - __bfloat162float(h1));
                    pl[j2][2 * hf + 1] = packf2(s[j][2] - __bfloat162float(h2),
                                                s[j][3] - __bfloat162float(h3));
                }
            }

#pragma unroll
            for (int j2 = 0; j2 < 4; j2++) {
#pragma unroll
                for (int nn = 0; nn < 8; nn++) {
                    uint32_t voff = (uint32_t)((j2 * 16 + v_kr) * ALD + nn * 16 + v_nc) * 2;
                    uint32_t vh01[2], vh23[2], vl01[2], vl23[2];
                    LDSM_X4_T(vh01[0], vh01[1], vh23[0], vh23[1], st + 2 * AKV_BYTES + voff);
                    LDSM_X4_T(vl01[0], vl01[1], vl23[0], vl23[1], st + 3 * AKV_BYTES + voff);
                    mma_bf16(o[2 * nn],     ph[j2], vh01);
                    mma_bf16(o[2 * nn + 1], ph[j2], vh23);
                    mma_bf16(o[2 * nn],     pl[j2], vh01);
                    mma_bf16(o[2 * nn + 1], pl[j2], vh23);
                    mma_bf16(o[2 * nn],     ph[j2], vl01);
                    mma_bf16(o[2 * nn + 1], ph[j2], vl23);
                }
            }
        }
        __syncthreads();
    }

    const float iA = 1.f / lA;
    const float iB = 1.f / lB;
    const size_t bA = (rowbase + rowA) * (size_t)INNER + h * HEAD_DIM + 2 * (l & 3);
    const size_t bB = bA + 8 * (size_t)INNER;
#pragma unroll
    for (int n = 0; n < 16; n++) {
        float vA0 = o[n][0] * iA, vA1 = o[n][1] * iA;
        float vB0 = o[n][2] * iB, vB1 = o[n][3] * iB;
        __nv_bfloat16 hA0 = __float2bfloat16(vA0), hA1 = __float2bfloat16(vA1);
        __nv_bfloat16 hB0 = __float2bfloat16(vB0), hB1 = __float2bfloat16(vB1);
        *(uint32_t*)(outh + bA + 8 * n) = pack2(hA0, hA1);
        *(uint32_t*)(outh + bB + 8 * n) = pack2(hB0, hB1);
        *(uint32_t*)(outl + bA + 8 * n) = packf2(vA0 - __bfloat162float(hA0),
                                                 vA1 - __bfloat162float(hA1));
        *(uint32_t*)(outl + bB + 8 * n) = packf2(vB0 - __bfloat162float(hB0),
                                                 vB1 - __bfloat162float(hB1));
    }
}

// ---------------------------------------------------------------------------
extern "C" void kernel_launch(void* const* d_in, const int* in_sizes, int n_in,
                              void* d_out, int out_size)
{
    const float* x      = (const float*)d_in[0];
    const float* W_qkv  = (const float*)d_in[1];
    const float* W_proj = (const float*)d_in[2];
    float* out = (float*)d_out;

    float *qkv_ptr;
    __nv_bfloat16 *qkvh, *qkvl, *xh, *xl, *wqh, *wql, *wph, *wpl, *ah, *al;
    cudaGetSymbolAddress((void**)&qkv_ptr, g_qkv);
    cudaGetSymbolAddress((void**)&qkvh, g_qkvh);
    cudaGetSymbolAddress((void**)&qkvl, g_qkvl);
    cudaGetSymbolAddress((void**)&xh, g_xh);
    cudaGetSymbolAddress((void**)&xl, g_xl);
    cudaGetSymbolAddress((void**)&wqh, g_wqh);
    cudaGetSymbolAddress((void**)&wql, g_wql);
    cudaGetSymbolAddress((void**)&wph, g_wph);
    cudaGetSymbolAddress((void**)&wpl, g_wpl);
    cudaGetSymbolAddress((void**)&ah, g_ah);
    cudaGetSymbolAddress((void**)&al, g_al);

    cudaFuncSetAttribute(gemm_bf16x3, cudaFuncAttributeMaxDynamicSharedMemorySize,
                         GEMM_SMEM);
    cudaFuncSetAttribute(attn_mma, cudaFuncAttributeMaxDynamicSharedMemorySize,
                         ATTN_SMEM);

    split_kernel<<<(MTOK * DIM / 4) / 256, 256>>>(x, xh, xl, MTOK * DIM / 4);
    split_kernel<<<(QKV_N * DIM / 4) / 256, 256>>>(W_qkv, wqh, wql, QKV_N * DIM / 4);
    split_kernel<<<(INNER * DIM / 4) / 256, 256>>>(W_proj, wph, wpl, INNER * DIM / 4);

    // 1) qkv = x @ W_qkv^T (HMMA, 128x256 tiles)
    gemm_bf16x3<<<dim3(QKV_N / GBN, MTOK / GBM), 256, GEMM_SMEM>>>(
        xh, xl, wqh, wql, qkv_ptr, MTOK, QKV_N, DIM);

    // 2) fused RoPE + split
    rope_split_kernel<<<(3 * B_ * T_ * HEADS * 64) / 256, 256>>>(qkv_ptr, qkvh, qkvl);

    // 3) HMMA causal flash attention
    attn_mma<<<dim3(T_ / 128, B_ * HEADS), 256, ATTN_SMEM>>>(qkvh, qkvl, ah, al);

    // 4) out = attn @ W_proj^T (HMMA)
    gemm_bf16x3<<<dim3(INNER / GBN, MTOK / GBM), 256, GEMM_SMEM>>>(
        ah, al, wph, wpl, out, MTOK, INNER, DIM);
}

// round 6
// speedup vs baseline: 3.4648x; 1.0769x over previous
#include <cuda_runtime.h>
#include <cuda_bf16.h>
#include <math.h>
#include <cstdint>

#define HEADS    16
#define HEAD_DIM 128
#define B_       2
#define T_       2048
#define DIM      2048
#define INNER    (HEADS * HEAD_DIM)   // 2048
#define QKV_N    (3 * INNER)          // 6144
#define MTOK     (B_ * T_)            // 4096

// ---------------------------------------------------------------------------
// Scratch (allocation-free rule: __device__ globals)
// ---------------------------------------------------------------------------
__device__ float g_qkv[(size_t)MTOK * QKV_N];    // fp32 qkv (pre-rope)
__device__ __nv_bfloat16 g_qkvh[(size_t)MTOK * QKV_N], g_qkvl[(size_t)MTOK * QKV_N];
__device__ __nv_bfloat16 g_xh[(size_t)MTOK * DIM],  g_xl[(size_t)MTOK * DIM];
__device__ __nv_bfloat16 g_wqh[(size_t)QKV_N * DIM], g_wql[(size_t)QKV_N * DIM];
__device__ __nv_bfloat16 g_wph[(size_t)INNER * DIM], g_wpl[(size_t)INNER * DIM];
__device__ __nv_bfloat16 g_ah[(size_t)MTOK * INNER], g_al[(size_t)MTOK * INNER];

// ---------------------------------------------------------------------------
// PTX helpers (baseline ISA only — plain sm_103 target)
// ---------------------------------------------------------------------------
__device__ __forceinline__ uint32_t smem_to_u32(const void* p) {
    uint32_t a;
    asm("{ .reg .u64 t; cvta.to.shared.u64 t, %1; cvt.u32.u64 %0, t; }"
        : "=r"(a) : "l"(p));
    return a;
}
__device__ __forceinline__ void cp_async16(uint32_t dst, const void* src) {
    asm volatile("cp.async.cg.shared.global [%0], [%1], 16;" :: "r"(dst), "l"(src));
}
#define CP_COMMIT() asm volatile("cp.async.commit_group;" ::: "memory")
#define CP_WAIT(n)  asm volatile("cp.async.wait_group %0;" :: "n"(n) : "memory")

#define LDSM_X4(r0, r1, r2, r3, addr) \
    asm volatile("ldmatrix.sync.aligned.m8n8.x4.shared.b16 {%0,%1,%2,%3}, [%4];" \
        : "=r"(r0), "=r"(r1), "=r"(r2), "=r"(r3) : "r"(addr))
#define LDSM_X4_T(r0, r1, r2, r3, addr) \
    asm volatile("ldmatrix.sync.aligned.m8n8.x4.trans.shared.b16 {%0,%1,%2,%3}, [%4];" \
        : "=r"(r0), "=r"(r1), "=r"(r2), "=r"(r3) : "r"(addr))

__device__ __forceinline__ void mma_bf16(float* c, const uint32_t* a, const uint32_t* b)
{
    asm volatile(
        "mma.sync.aligned.m16n8k16.row.col.f32.bf16.bf16.f32 "
        "{%0,%1,%2,%3}, {%4,%5,%6,%7}, {%8,%9}, {%0,%1,%2,%3};"
        : "+f"(c[0]), "+f"(c[1]), "+f"(c[2]), "+f"(c[3])
        : "r"(a[0]), "r"(a[1]), "r"(a[2]), "r"(a[3]), "r"(b[0]), "r"(b[1]));
}

__device__ __forceinline__ uint32_t pack2(__nv_bfloat16 a, __nv_bfloat16 b) {
    __nv_bfloat162 t(a, b);
    return *reinterpret_cast<uint32_t*>(&t);
}
__device__ __forceinline__ uint32_t packf2(float lo, float hi) {
    __nv_bfloat162 t = __floats2bfloat162_rn(lo, hi);
    return *reinterpret_cast<uint32_t*>(&t);
}

// ---------------------------------------------------------------------------
// Split fp32 -> (hi bf16, lo bf16)
// ---------------------------------------------------------------------------
__global__ void split_kernel(const float* __restrict__ src,
                             __nv_bfloat16* __restrict__ hi,
                             __nv_bfloat16* __restrict__ lo, int n4)
{
    int i = blockIdx.x * 256 + threadIdx.x;
    if (i >= n4) return;
    float4 v = ((const float4*)src)[i];
    float f[4] = {v.x, v.y, v.z, v.w};
    __nv_bfloat162 h2[2], l2[2];
#pragma unroll
    for (int j = 0; j < 2; j++) {
        __nv_bfloat16 h0 = __float2bfloat16(f[2 * j]);
        __nv_bfloat16 h1 = __float2bfloat16(f[2 * j + 1]);
        __nv_bfloat16 l0 = __float2bfloat16(f[2 * j] - __bfloat162float(h0));
        __nv_bfloat16 l1 = __float2bfloat16(f[2 * j + 1] - __bfloat162float(h1));
        h2[j] = __nv_bfloat162(h0, h1);
        l2[j] = __nv_bfloat162(l0, l1);
    }
    ((__nv_bfloat162*)hi)[2 * i]     = h2[0];
    ((__nv_bfloat162*)hi)[2 * i + 1] = h2[1];
    ((__nv_bfloat162*)lo)[2 * i]     = l2[0];
    ((__nv_bfloat162*)lo)[2 * i + 1] = l2[1];
}

// ---------------------------------------------------------------------------
// Fused RoPE + hi/lo split
// ---------------------------------------------------------------------------
__global__ void rope_split_kernel(const float* __restrict__ qkv,
                                  __nv_bfloat16* __restrict__ qh,
                                  __nv_bfloat16* __restrict__ ql)
{
    int idx = blockIdx.x * 256 + threadIdx.x;
    int i   = idx & 63;
    int h   = (idx >> 6) & 15;
    int t   = (idx >> 10) & 2047;
    int b   = (idx >> 21) & 1;
    int sec = idx >> 22;             // 0=q,1=k,2=v

    size_t base = (size_t)(b * T_ + t) * QKV_N + sec * INNER + h * HEAD_DIM + i;
    float x1 = qkv[base];
    float x2 = qkv[base + 64];
    float y1 = x1, y2 = x2;
    if (sec < 2) {
        float inv = exp2f(-(float)i * 0.20761871929656223f);  // log2(1e4)/64
        float ang = (float)t * inv;
        float sn, cs;
        sincosf(ang, &sn, &cs);
        y1 = x1 * cs - x2 * sn;
        y2 = x2 * cs + x1 * sn;
    }
    __nv_bfloat16 h1 = __float2bfloat16(y1);
    __nv_bfloat16 h2 = __float2bfloat16(y2);
    qh[base]      = h1;
    qh[base + 64] = h2;
    ql[base]      = __float2bfloat16(y1 - __bfloat162float(h1));
    ql[base + 64] = __float2bfloat16(y2 - __bfloat162float(h2));
}

// ---------------------------------------------------------------------------
// HMMA GEMM v3: C[M,N](fp32) = (Ah+Al) @ (Bh+Bl)^T, 3-term bf16 split.
// Tile 128x128, BK=32, 8 warps (2x4), warp tile 64x32. 2-stage cp.async.
// Register-lean inner loop (A-frags streamed per-mi) -> 2 CTAs/SM.
// ---------------------------------------------------------------------------
#define GBM 128
#define GBN 128
#define GBK 32
#define LDA 40
#define MAT_BYTES (128 * LDA * 2)           // 10240
#define STAGE_BYTES (4 * MAT_BYTES)         // 40960
#define GEMM_SMEM (2 * STAGE_BYTES)         // 81920 per CTA -> 2 CTAs/SM

__device__ __forceinline__ void issue_stage(
    const __nv_bfloat16* __restrict__ Ah, const __nv_bfloat16* __restrict__ Al,
    const __nv_bfloat16* __restrict__ Bh, const __nv_bfloat16* __restrict__ Bl,
    size_t bm, size_t bn, int K, int k0, uint32_t sbase, int tid)
{
#pragma unroll
    for (int i = 0; i < 2; i++) {
        int idx = tid + i * 256;            // 0..511
        int r   = idx >> 2;                 // 0..127
        int c   = (idx & 3) << 3;           // 0,8,16,24
        uint32_t doff = (uint32_t)(r * LDA + c) * 2;
        size_t asrc = (bm + (size_t)r) * K + k0 + c;
        size_t bsrc = (bn + (size_t)r) * K + k0 + c;
        cp_async16(sbase + doff,                 Ah + asrc);
        cp_async16(sbase + MAT_BYTES + doff,     Al + asrc);
        cp_async16(sbase + 2 * MAT_BYTES + doff, Bh + bsrc);
        cp_async16(sbase + 3 * MAT_BYTES + doff, Bl + bsrc);
    }
}

__global__ __launch_bounds__(256, 2)
void gemm_bf16x3(const __nv_bfloat16* __restrict__ Ah, const __nv_bfloat16* __restrict__ Al,
                 const __nv_bfloat16* __restrict__ Bh, const __nv_bfloat16* __restrict__ Bl,
                 float* __restrict__ C, int M, int N, int K)
{
    extern __shared__ char smem[];
    const uint32_t s0 = smem_to_u32(smem);

    const int tid = threadIdx.x;
    const int wid = tid >> 5;
    const int l   = tid & 31;
    const int warp_m = wid & 1;             // 2 in M -> 64 rows
    const int warp_n = wid >> 1;            // 4 in N -> 32 cols
    const size_t bm = (size_t)blockIdx.y * GBM;
    const size_t bn = (size_t)blockIdx.x * GBN;

    float acc[4][4][4];
#pragma unroll
    for (int mi = 0; mi < 4; mi++)
#pragma unroll
        for (int ni = 0; ni < 4; ni++)
#pragma unroll
            for (int e = 0; e < 4; e++) acc[mi][ni][e] = 0.f;

    const int S = K / GBK;
    issue_stage(Ah, Al, Bh, Bl, bm, bn, K, 0, s0, tid);
    CP_COMMIT();

    const int a_row = warp_m * 64 + (l & 15);
    const int a_ch  = (l >> 4) << 3;
    const int g     = l >> 3;
    const int b_row = warp_n * 32 + ((g >> 1) << 3) + (l & 7);
    const int b_ch  = (g & 1) << 3;

    for (int s = 0; s < S; s++) {
        if (s + 1 < S) {
            issue_stage(Ah, Al, Bh, Bl, bm, bn, K, (s + 1) * GBK,
                        s0 + ((s + 1) & 1) * STAGE_BYTES, tid);
            CP_COMMIT();
            CP_WAIT(1);
        } else {
            CP_WAIT(0);
        }
        __syncthreads();

        const uint32_t ahB = s0 + (s & 1) * STAGE_BYTES;
        const uint32_t alB = ahB + MAT_BYTES;
        const uint32_t bhB = ahB + 2 * MAT_BYTES;
        const uint32_t blB = ahB + 3 * MAT_BYTES;

#pragma unroll
        for (int ks = 0; ks < 2; ks++) {
            const int kc = ks * 16;
            // B fragments resident across the mi loop (16 regs)
            uint32_t bh[4][2], bl[4][2];
#pragma unroll
            for (int nt = 0; nt < 2; nt++) {
                uint32_t off = (uint32_t)((b_row + nt * 16) * LDA + kc + b_ch) * 2;
                LDSM_X4(bh[2 * nt][0], bh[2 * nt][1], bh[2 * nt + 1][0], bh[2 * nt + 1][1], bhB + off);
                LDSM_X4(bl[2 * nt][0], bl[2 * nt][1], bl[2 * nt + 1][0], bl[2 * nt + 1][1], blB + off);
            }
            // A fragments streamed per-mi (8 regs live)
#pragma unroll
            for (int mi = 0; mi < 4; mi++) {
                uint32_t ah[4], al[4];
                uint32_t off = (uint32_t)((a_row + mi * 16) * LDA + kc + a_ch) * 2;
                LDSM_X4(ah[0], ah[1], ah[2], ah[3], ahB + off);
                LDSM_X4(al[0], al[1], al[2], al[3], alB + off);
#pragma unroll
                for (int ni = 0; ni < 4; ni++)
                    mma_bf16(acc[mi][ni], ah, bh[ni]);
#pragma unroll
                for (int ni = 0; ni < 4; ni++)
                    mma_bf16(acc[mi][ni], al, bh[ni]);
#pragma unroll
                for (int ni = 0; ni < 4; ni++)
                    mma_bf16(acc[mi][ni], ah, bl[ni]);
            }
        }
        __syncthreads();
    }

    const size_t row0 = bm + warp_m * 64 + (l >> 2);
    const int    col0 = (int)bn + warp_n * 32 + 2 * (l & 3);
#pragma unroll
    for (int mi = 0; mi < 4; mi++) {
#pragma unroll
        for (int ni = 0; ni < 4; ni++) {
            float* p0 = C + (row0 + mi * 16) * N + col0 + ni * 8;
            float* p1 = p0 + 8 * (size_t)N;
            *(float2*)p0 = make_float2(acc[mi][ni][0], acc[mi][ni][1]);
            *(float2*)p1 = make_float2(acc[mi][ni][2], acc[mi][ni][3]);
        }
    }
}

// ---------------------------------------------------------------------------
// HMMA causal flash attention with hi/lo splits (unchanged from round 4).
// ---------------------------------------------------------------------------
#define ALD 136
#define AQ_BYTES   (128 * ALD * 2)
#define AKV_BYTES  (64 * ALD * 2)
#define AKV_STAGE  (4 * AKV_BYTES)
#define ATTN_SMEM  (2 * AQ_BYTES + 2 * AKV_STAGE)

__global__ __launch_bounds__(256, 1)
void attn_mma(const __nv_bfloat16* __restrict__ QKVh,
              const __nv_bfloat16* __restrict__ QKVl,
              __nv_bfloat16* __restrict__ outh,
              __nv_bfloat16* __restrict__ outl)
{
    extern __shared__ char smem[];
    const uint32_t s0  = smem_to_u32(smem);
    const uint32_t qhB = s0;
    const uint32_t qlB = s0 + AQ_BYTES;
    const uint32_t kvB = s0 + 2 * AQ_BYTES;

    const int tid = threadIdx.x;
    const int wid = tid >> 5;
    const int l   = tid & 31;
    const int qb  = (int)gridDim.x - 1 - (int)blockIdx.x;
    const int b   = (int)blockIdx.y >> 4;
    const int h   = (int)blockIdx.y & 15;
    const int q0  = qb * 128;
    const size_t rowbase = (size_t)b * T_;
    const float scale = 0.08838834764831843f;

#pragma unroll
    for (int it = 0; it < 16; it++) {
        int idx = tid + it * 256;
        int mat = idx >> 11;
        int r   = (idx >> 4) & 127;
        int c   = idx & 15;
        const __nv_bfloat16* src = (mat ? QKVl : QKVh) +
            (rowbase + q0 + r) * QKV_N + h * HEAD_DIM + c * 8;
        cp_async16((mat ? qlB : qhB) + (uint32_t)(r * ALD + c * 8) * 2, src);
    }

    auto issue_kv = [&](int kv0, int buf) {
        uint32_t base = kvB + (uint32_t)buf * AKV_STAGE;
#pragma unroll
        for (int it = 0; it < 16; it++) {
            int idx = tid + it * 256;
            int m   = idx >> 10;
            int r   = (idx >> 4) & 63;
            int c   = idx & 15;
            const __nv_bfloat16* p = (m & 1) ? QKVl : QKVh;
            int sect = (m >> 1) ? 2 * INNER : INNER;
            const __nv_bfloat16* src = p +
                (rowbase + kv0 + r) * QKV_N + sect + h * HEAD_DIM + c * 8;
            cp_async16(base + (uint32_t)m * AKV_BYTES + (uint32_t)(r * ALD + c * 8) * 2, src);
        }
    };

    const int a_row  = wid * 16 + (l & 15);
    const int a_ch   = (l >> 4) << 3;
    const int g      = l >> 3;
    const int bn_row = ((g >> 1) << 3) + (l & 7);
    const int b_ch   = (g & 1) << 3;
    const int v_kr   = (((l >> 3) & 1) << 3) + (l & 7);
    const int v_nc   = (l >> 4) << 3;

    float o[16][4];
#pragma unroll
    for (int n = 0; n < 16; n++)
#pragma unroll
        for (int e = 0; e < 4; e++) o[n][e] = 0.f;
    float mA = -INFINITY, mB = -INFINITY, lA = 0.f, lB = 0.f;

    const int ntiles = 2 * qb + 2;
    issue_kv(0, 0);
    CP_COMMIT();

    const int row0 = q0 + wid * 16;
    const int r0l  = l >> 2;
    const int rowA = row0 + r0l;
    const int rowB = rowA + 8;

    for (int t = 0; t < ntiles; t++) {
        if (t + 1 < ntiles) {
            issue_kv((t + 1) * 64, (t + 1) & 1);
            CP_COMMIT();
            CP_WAIT(1);
        } else {
            CP_WAIT(0);
        }
        __syncthreads();

        const int kv0 = t * 64;
        const uint32_t st = kvB + (uint32_t)(t & 1) * AKV_STAGE;

        if (kv0 <= row0 + 15) {
            float s[8][4];
#pragma unroll
            for (int n = 0; n < 8; n++)
#pragma unroll
                for (int e = 0; e < 4; e++) s[n][e] = 0.f;

#pragma unroll
            for (int kk = 0; kk < 8; kk++) {
                const int kc = kk * 16;
                uint32_t qa[4], qla[4], kh[8][2], kl[8][2];
                uint32_t qoff = (uint32_t)(a_row * ALD + kc + a_ch) * 2;
                LDSM_X4(qa[0], qa[1], qa[2], qa[3], qhB + qoff);
                LDSM_X4(qla[0], qla[1], qla[2], qla[3], qlB + qoff);
#pragma unroll
                for (int nt = 0; nt < 4; nt++) {
                    uint32_t koff = (uint32_t)((nt * 16 + bn_row) * ALD + kc + b_ch) * 2;
                    LDSM_X4(kh[2 * nt][0], kh[2 * nt][1], kh[2 * nt + 1][0], kh[2 * nt + 1][1],
                            st + koff);
                    LDSM_X4(kl[2 * nt][0], kl[2 * nt][1], kl[2 * nt + 1][0], kl[2 * nt + 1][1],
                            st + AKV_BYTES + koff);
                }
#pragma unroll
                for (int n = 0; n < 8; n++) {
                    mma_bf16(s[n], qa,  kh[n]);
                    mma_bf16(s[n], qla, kh[n]);
                    mma_bf16(s[n], qa,  kl[n]);
                }
            }

#pragma unroll
            for (int n = 0; n < 8; n++)
#pragma unroll
                for (int e = 0; e < 4; e++) s[n][e] *= scale;

            if (kv0 + 63 > row0) {
                const int cb = kv0 + 2 * (l & 3);
#pragma unroll
                for (int n = 0; n < 8; n++) {
                    int c0 = cb + 8 * n;
                    if (c0     > rowA) s[n][0] = -INFINITY;
                    if (c0 + 1 > rowA) s[n][1] = -INFINITY;
                    if (c0     > rowB) s[n][2] = -INFINITY;
                    if (c0 + 1 > rowB) s[n][3] = -INFINITY;
                }
            }

            float mxA = -INFINITY, mxB = -INFINITY;
#pragma unroll
            for (int n = 0; n < 8; n++) {
                mxA = fmaxf(mxA, fmaxf(s[n][0], s[n][1]));
                mxB = fmaxf(mxB, fmaxf(s[n][2], s[n][3]));
            }
#pragma unroll
            for (int off = 1; off < 4; off <<= 1) {
                mxA = fmaxf(mxA, __shfl_xor_sync(0xffffffffu, mxA, off));
                mxB = fmaxf(mxB, __shfl_xor_sync(0xffffffffu, mxB, off));
            }
            float mnA = fmaxf(mA, mxA), mnB = fmaxf(mB, mxB);
            float cA = __expf(mA - mnA), cB = __expf(mB - mnB);
            float rsA = 0.f, rsB = 0.f;
#pragma unroll
            for (int n = 0; n < 8; n++) {
                s[n][0] = __expf(s[n][0] - mnA);
                s[n][1] = __expf(s[n][1] - mnA);
                s[n][2] = __expf(s[n][2] - mnB);
                s[n][3] = __expf(s[n][3] - mnB);
                rsA += s[n][0] + s[n][1];
                rsB += s[n][2] + s[n][3];
            }
#pragma unroll
            for (int off = 1; off < 4; off <<= 1) {
                rsA += __shfl_xor_sync(0xffffffffu, rsA, off);
                rsB += __shfl_xor_sync(0xffffffffu, rsB, off);
            }
            lA = lA * cA + rsA;  mA = mnA;
            lB = lB * cB + rsB;  mB = mnB;
#pragma unroll
            for (int n = 0; n < 16; n++) {
                o[n][0] *= cA; o[n][1] *= cA;
                o[n][2] *= cB; o[n][3] *= cB;
            }

            uint32_t ph[4][4], pl[4][4];
#pragma unroll
            for (int j2 = 0; j2 < 4; j2++) {
#pragma unroll
                for (int hf = 0; hf < 2; hf++) {
                    int j = 2 * j2 + hf;
                    __nv_bfloat16 h0 = __float2bfloat16(s[j][0]);
                    __nv_bfloat16 h1 = __float2bfloat16(s[j][1]);
                    __nv_bfloat16 h2 = __float2bfloat16(s[j][2]);
                    __nv_bfloat16 h3 = __float2bfloat16(s[j][3]);
                    ph[j2][2 * hf]     = pack2(h0, h1);
                    ph[j2][2 * hf + 1] = pack2(h2, h3);
                    pl[j2][2 * hf]     = packf2(s[j][0] - __bfloat162float(h0),
                                                s[j][1] - __bfloat162float(h1));
                    pl[j2][2 * hf + 1] = packf2(s[j][2] - __bfloat162float(h2),
                                                s[j][3] - __bfloat162float(h3));
                }
            }

#pragma unroll
            for (int j2 = 0; j2 < 4; j2++) {
#pragma unroll
                for (int nn = 0; nn < 8; nn++) {
                    uint32_t voff = (uint32_t)((j2 * 16 + v_kr) * ALD + nn * 16 + v_nc) * 2;
                    uint32_t vh01[2], vh23[2], vl01[2], vl23[2];
                    LDSM_X4_T(vh01[0], vh01[1], vh23[0], vh23[1], st + 2 * AKV_BYTES + voff);
                    LDSM_X4_T(vl01[0], vl01[1], vl23[0], vl23[1], st + 3 * AKV_BYTES + voff);
                    mma_bf16(o[2 * nn],     ph[j2], vh01);
                    mma_bf16(o[2 * nn + 1], ph[j2], vh23);
                    mma_bf16(o[2 * nn],     pl[j2], vh01);
                    mma_bf16(o[2 * nn + 1], pl[j2], vh23);
                    mma_bf16(o[2 * nn],     ph[j2], vl01);
                    mma_bf16(o[2 * nn + 1], ph[j2], vl23);
                }
            }
        }
        __syncthreads();
    }

    const float iA = 1.f / lA;
    const float iB = 1.f / lB;
    const size_t bA = (rowbase + rowA) * (size_t)INNER + h * HEAD_DIM + 2 * (l & 3);
    const size_t bB = bA + 8 * (size_t)INNER;
#pragma unroll
    for (int n = 0; n < 16; n++) {
        float vA0 = o[n][0] * iA, vA1 = o[n][1] * iA;
        float vB0 = o[n][2] * iB, vB1 = o[n][3] * iB;
        __nv_bfloat16 hA0 = __float2bfloat16(vA0), hA1 = __float2bfloat16(vA1);
        __nv_bfloat16 hB0 = __float2bfloat16(vB0), hB1 = __float2bfloat16(vB1);
        *(uint32_t*)(outh + bA + 8 * n) = pack2(hA0, hA1);
        *(uint32_t*)(outh + bB + 8 * n) = pack2(hB0, hB1);
        *(uint32_t*)(outl + bA + 8 * n) = packf2(vA0 - __bfloat162float(hA0),
                                                 vA1 - __bfloat162float(hA1));
        *(uint32_t*)(outl + bB + 8 * n) = packf2(vB0 - __bfloat162float(hB0),
                                                 vB1 - __bfloat162float(hB1));
    }
}

// ---------------------------------------------------------------------------
extern "C" void kernel_launch(void* const* d_in, const int* in_sizes, int n_in,
                              void* d_out, int out_size)
{
    const float* x      = (const float*)d_in[0];
    const float* W_qkv  = (const float*)d_in[1];
    const float* W_proj = (const float*)d_in[2];
    float* out = (float*)d_out;

    float *qkv_ptr;
    __nv_bfloat16 *qkvh, *qkvl, *xh, *xl, *wqh, *wql, *wph, *wpl, *ah, *al;
    cudaGetSymbolAddress((void**)&qkv_ptr, g_qkv);
    cudaGetSymbolAddress((void**)&qkvh, g_qkvh);
    cudaGetSymbolAddress((void**)&qkvl, g_qkvl);
    cudaGetSymbolAddress((void**)&xh, g_xh);
    cudaGetSymbolAddress((void**)&xl, g_xl);
    cudaGetSymbolAddress((void**)&wqh, g_wqh);
    cudaGetSymbolAddress((void**)&wql, g_wql);
    cudaGetSymbolAddress((void**)&wph, g_wph);
    cudaGetSymbolAddress((void**)&wpl, g_wpl);
    cudaGetSymbolAddress((void**)&ah, g_ah);
    cudaGetSymbolAddress((void**)&al, g_al);

    cudaFuncSetAttribute(gemm_bf16x3, cudaFuncAttributeMaxDynamicSharedMemorySize,
                         GEMM_SMEM);
    cudaFuncSetAttribute(attn_mma, cudaFuncAttributeMaxDynamicSharedMemorySize,
                         ATTN_SMEM);

    split_kernel<<<(MTOK * DIM / 4) / 256, 256>>>(x, xh, xl, MTOK * DIM / 4);
    split_kernel<<<(QKV_N * DIM / 4) / 256, 256>>>(W_qkv, wqh, wql, QKV_N * DIM / 4);
    split_kernel<<<(INNER * DIM / 4) / 256, 256>>>(W_proj, wph, wpl, INNER * DIM / 4);

    // 1) qkv = x @ W_qkv^T (HMMA, 128x128 tiles, 2 CTAs/SM)
    gemm_bf16x3<<<dim3(QKV_N / GBN, MTOK / GBM), 256, GEMM_SMEM>>>(
        xh, xl, wqh, wql, qkv_ptr, MTOK, QKV_N, DIM);

    // 2) fused RoPE + split
    rope_split_kernel<<<(3 * B_ * T_ * HEADS * 64) / 256, 256>>>(qkv_ptr, qkvh, qkvl);

    // 3) HMMA causal flash attention
    attn_mma<<<dim3(T_ / 128, B_ * HEADS), 256, ATTN_SMEM>>>(qkvh, qkvl, ah, al);

    // 4) out = attn @ W_proj^T (HMMA)
    gemm_bf16x3<<<dim3(INNER / GBN, MTOK / GBM), 256, GEMM_SMEM>>>(
        ah, al, wph, wpl, out, MTOK, INNER, DIM);
}

// round 7
// speedup vs baseline: 3.4866x; 1.0063x over previous
#include <cuda_runtime.h>
#include <cuda_bf16.h>
#include <math.h>
#include <cstdint>

#define HEADS    16
#define HEAD_DIM 128
#define B_       2
#define T_       2048
#define DIM      2048
#define INNER    (HEADS * HEAD_DIM)   // 2048
#define QKV_N    (3 * INNER)          // 6144
#define MTOK     (B_ * T_)            // 4096

// ---------------------------------------------------------------------------
// Scratch (allocation-free rule: __device__ globals)
// ---------------------------------------------------------------------------
__device__ float g_qkv[(size_t)MTOK * QKV_N];    // fp32 qkv (pre-rope)
__device__ __nv_bfloat16 g_qkvh[(size_t)MTOK * QKV_N], g_qkvl[(size_t)MTOK * QKV_N];
__device__ __nv_bfloat16 g_xh[(size_t)MTOK * DIM],  g_xl[(size_t)MTOK * DIM];
__device__ __nv_bfloat16 g_wqh[(size_t)QKV_N * DIM], g_wql[(size_t)QKV_N * DIM];
__device__ __nv_bfloat16 g_wph[(size_t)INNER * DIM], g_wpl[(size_t)INNER * DIM];
__device__ __nv_bfloat16 g_ah[(size_t)MTOK * INNER], g_al[(size_t)MTOK * INNER];

// ---------------------------------------------------------------------------
// PTX helpers (baseline ISA only — plain sm_103 target)
// ---------------------------------------------------------------------------
__device__ __forceinline__ uint32_t smem_to_u32(const void* p) {
    uint32_t a;
    asm("{ .reg .u64 t; cvta.to.shared.u64 t, %1; cvt.u32.u64 %0, t; }"
        : "=r"(a) : "l"(p));
    return a;
}
__device__ __forceinline__ void cp_async16(uint32_t dst, const void* src) {
    asm volatile("cp.async.cg.shared.global [%0], [%1], 16;" :: "r"(dst), "l"(src));
}
#define CP_COMMIT() asm volatile("cp.async.commit_group;" ::: "memory")
#define CP_WAIT(n)  asm volatile("cp.async.wait_group %0;" :: "n"(n) : "memory")

#define LDSM_X4(r0, r1, r2, r3, addr) \
    asm volatile("ldmatrix.sync.aligned.m8n8.x4.shared.b16 {%0,%1,%2,%3}, [%4];" \
        : "=r"(r0), "=r"(r1), "=r"(r2), "=r"(r3) : "r"(addr))
#define LDSM_X4_T(r0, r1, r2, r3, addr) \
    asm volatile("ldmatrix.sync.aligned.m8n8.x4.trans.shared.b16 {%0,%1,%2,%3}, [%4];" \
        : "=r"(r0), "=r"(r1), "=r"(r2), "=r"(r3) : "r"(addr))

__device__ __forceinline__ void mma_bf16(float* c, const uint32_t* a, const uint32_t* b)
{
    asm volatile(
        "mma.sync.aligned.m16n8k16.row.col.f32.bf16.bf16.f32 "
        "{%0,%1,%2,%3}, {%4,%5,%6,%7}, {%8,%9}, {%0,%1,%2,%3};"
        : "+f"(c[0]), "+f"(c[1]), "+f"(c[2]), "+f"(c[3])
        : "r"(a[0]), "r"(a[1]), "r"(a[2]), "r"(a[3]), "r"(b[0]), "r"(b[1]));
}

__device__ __forceinline__ uint32_t pack2(__nv_bfloat16 a, __nv_bfloat16 b) {
    __nv_bfloat162 t(a, b);
    return *reinterpret_cast<uint32_t*>(&t);
}
__device__ __forceinline__ uint32_t packf2(float lo, float hi) {
    __nv_bfloat162 t = __floats2bfloat162_rn(lo, hi);
    return *reinterpret_cast<uint32_t*>(&t);
}

// ---------------------------------------------------------------------------
// Split fp32 -> (hi bf16, lo bf16)
// ---------------------------------------------------------------------------
__global__ void split_kernel(const float* __restrict__ src,
                             __nv_bfloat16* __restrict__ hi,
                             __nv_bfloat16* __restrict__ lo, int n4)
{
    int i = blockIdx.x * 256 + threadIdx.x;
    if (i >= n4) return;
    float4 v = ((const float4*)src)[i];
    float f[4] = {v.x, v.y, v.z, v.w};
    __nv_bfloat162 h2[2], l2[2];
#pragma unroll
    for (int j = 0; j < 2; j++) {
        __nv_bfloat16 h0 = __float2bfloat16(f[2 * j]);
        __nv_bfloat16 h1 = __float2bfloat16(f[2 * j + 1]);
        __nv_bfloat16 l0 = __float2bfloat16(f[2 * j] - __bfloat162float(h0));
        __nv_bfloat16 l1 = __float2bfloat16(f[2 * j + 1] - __bfloat162float(h1));
        h2[j] = __nv_bfloat162(h0, h1);
        l2[j] = __nv_bfloat162(l0, l1);
    }
    ((__nv_bfloat162*)hi)[2 * i]     = h2[0];
    ((__nv_bfloat162*)hi)[2 * i + 1] = h2[1];
    ((__nv_bfloat162*)lo)[2 * i]     = l2[0];
    ((__nv_bfloat162*)lo)[2 * i + 1] = l2[1];
}

// ---------------------------------------------------------------------------
// Fused RoPE + hi/lo split
// ---------------------------------------------------------------------------
__global__ void rope_split_kernel(const float* __restrict__ qkv,
                                  __nv_bfloat16* __restrict__ qh,
                                  __nv_bfloat16* __restrict__ ql)
{
    int idx = blockIdx.x * 256 + threadIdx.x;
    int i   = idx & 63;
    int h   = (idx >> 6) & 15;
    int t   = (idx >> 10) & 2047;
    int b   = (idx >> 21) & 1;
    int sec = idx >> 22;             // 0=q,1=k,2=v

    size_t base = (size_t)(b * T_ + t) * QKV_N + sec * INNER + h * HEAD_DIM + i;
    float x1 = qkv[base];
    float x2 = qkv[base + 64];
    float y1 = x1, y2 = x2;
    if (sec < 2) {
        float inv = exp2f(-(float)i * 0.20761871929656223f);  // log2(1e4)/64
        float ang = (float)t * inv;
        float sn, cs;
        sincosf(ang, &sn, &cs);
        y1 = x1 * cs - x2 * sn;
        y2 = x2 * cs + x1 * sn;
    }
    __nv_bfloat16 h1 = __float2bfloat16(y1);
    __nv_bfloat16 h2 = __float2bfloat16(y2);
    qh[base]      = h1;
    qh[base + 64] = h2;
    ql[base]      = __float2bfloat16(y1 - __bfloat162float(h1));
    ql[base + 64] = __float2bfloat16(y2 - __bfloat162float(h2));
}

// ---------------------------------------------------------------------------
// HMMA GEMM v4: C[M,N](fp32) = (Ah+Al) @ (Bh+Bl)^T, 3-term bf16 split.
// Tile 128x128, BK=32, 8 warps (2x4), warp tile 64x32. 2-stage cp.async.
// mi processed in PAIRS -> 8 independent acc chains, while staying <=128 regs
// for 2 CTAs/SM.
// ---------------------------------------------------------------------------
#define GBM 128
#define GBN 128
#define GBK 32
#define LDA 40
#define MAT_BYTES (128 * LDA * 2)           // 10240
#define STAGE_BYTES (4 * MAT_BYTES)         // 40960
#define GEMM_SMEM (2 * STAGE_BYTES)         // 81920 per CTA -> 2 CTAs/SM

__device__ __forceinline__ void issue_stage(
    const __nv_bfloat16* __restrict__ Ah, const __nv_bfloat16* __restrict__ Al,
    const __nv_bfloat16* __restrict__ Bh, const __nv_bfloat16* __restrict__ Bl,
    size_t bm, size_t bn, int K, int k0, uint32_t sbase, int tid)
{
#pragma unroll
    for (int i = 0; i < 2; i++) {
        int idx = tid + i * 256;            // 0..511
        int r   = idx >> 2;                 // 0..127
        int c   = (idx & 3) << 3;           // 0,8,16,24
        uint32_t doff = (uint32_t)(r * LDA + c) * 2;
        size_t asrc = (bm + (size_t)r) * K + k0 + c;
        size_t bsrc = (bn + (size_t)r) * K + k0 + c;
        cp_async16(sbase + doff,                 Ah + asrc);
        cp_async16(sbase + MAT_BYTES + doff,     Al + asrc);
        cp_async16(sbase + 2 * MAT_BYTES + doff, Bh + bsrc);
        cp_async16(sbase + 3 * MAT_BYTES + doff, Bl + bsrc);
    }
}

__global__ __launch_bounds__(256, 2)
void gemm_bf16x3(const __nv_bfloat16* __restrict__ Ah, const __nv_bfloat16* __restrict__ Al,
                 const __nv_bfloat16* __restrict__ Bh, const __nv_bfloat16* __restrict__ Bl,
                 float* __restrict__ C, int M, int N, int K)
{
    extern __shared__ char smem[];
    const uint32_t s0 = smem_to_u32(smem);

    const int tid = threadIdx.x;
    const int wid = tid >> 5;
    const int l   = tid & 31;
    const int warp_m = wid & 1;             // 2 in M -> 64 rows
    const int warp_n = wid >> 1;            // 4 in N -> 32 cols
    const size_t bm = (size_t)blockIdx.y * GBM;
    const size_t bn = (size_t)blockIdx.x * GBN;

    float acc[4][4][4];
#pragma unroll
    for (int mi = 0; mi < 4; mi++)
#pragma unroll
        for (int ni = 0; ni < 4; ni++)
#pragma unroll
            for (int e = 0; e < 4; e++) acc[mi][ni][e] = 0.f;

    const int S = K / GBK;
    issue_stage(Ah, Al, Bh, Bl, bm, bn, K, 0, s0, tid);
    CP_COMMIT();

    const int a_row = warp_m * 64 + (l & 15);
    const int a_ch  = (l >> 4) << 3;
    const int g     = l >> 3;
    const int b_row = warp_n * 32 + ((g >> 1) << 3) + (l & 7);
    const int b_ch  = (g & 1) << 3;

    for (int s = 0; s < S; s++) {
        if (s + 1 < S) {
            issue_stage(Ah, Al, Bh, Bl, bm, bn, K, (s + 1) * GBK,
                        s0 + ((s + 1) & 1) * STAGE_BYTES, tid);
            CP_COMMIT();
            CP_WAIT(1);
        } else {
            CP_WAIT(0);
        }
        __syncthreads();

        const uint32_t ahB = s0 + (s & 1) * STAGE_BYTES;
        const uint32_t alB = ahB + MAT_BYTES;
        const uint32_t bhB = ahB + 2 * MAT_BYTES;
        const uint32_t blB = ahB + 3 * MAT_BYTES;

#pragma unroll
        for (int ks = 0; ks < 2; ks++) {
            const int kc = ks * 16;
            // B fragments resident (16 regs)
            uint32_t bh[4][2], bl[4][2];
#pragma unroll
            for (int nt = 0; nt < 2; nt++) {
                uint32_t off = (uint32_t)((b_row + nt * 16) * LDA + kc + b_ch) * 2;
                LDSM_X4(bh[2 * nt][0], bh[2 * nt][1], bh[2 * nt + 1][0], bh[2 * nt + 1][1], bhB + off);
                LDSM_X4(bl[2 * nt][0], bl[2 * nt][1], bl[2 * nt + 1][0], bl[2 * nt + 1][1], blB + off);
            }
            // A fragments for a PAIR of mi tiles (16 regs) -> 8 indep chains
#pragma unroll
            for (int mp = 0; mp < 2; mp++) {
                const int mi0 = 2 * mp, mi1 = 2 * mp + 1;
                uint32_t ah0[4], al0[4], ah1[4], al1[4];
                uint32_t off0 = (uint32_t)((a_row + mi0 * 16) * LDA + kc + a_ch) * 2;
                uint32_t off1 = (uint32_t)((a_row + mi1 * 16) * LDA + kc + a_ch) * 2;
                LDSM_X4(ah0[0], ah0[1], ah0[2], ah0[3], ahB + off0);
                LDSM_X4(ah1[0], ah1[1], ah1[2], ah1[3], ahB + off1);
                LDSM_X4(al0[0], al0[1], al0[2], al0[3], alB + off0);
                LDSM_X4(al1[0], al1[1], al1[2], al1[3], alB + off1);
#pragma unroll
                for (int ni = 0; ni < 4; ni++) {
                    mma_bf16(acc[mi0][ni], ah0, bh[ni]);
                    mma_bf16(acc[mi1][ni], ah1, bh[ni]);
                }
#pragma unroll
                for (int ni = 0; ni < 4; ni++) {
                    mma_bf16(acc[mi0][ni], al0, bh[ni]);
                    mma_bf16(acc[mi1][ni], al1, bh[ni]);
                }
#pragma unroll
                for (int ni = 0; ni < 4; ni++) {
                    mma_bf16(acc[mi0][ni], ah0, bl[ni]);
                    mma_bf16(acc[mi1][ni], ah1, bl[ni]);
                }
            }
        }
        __syncthreads();
    }

    const size_t row0 = bm + warp_m * 64 + (l >> 2);
    const int    col0 = (int)bn + warp_n * 32 + 2 * (l & 3);
#pragma unroll
    for (int mi = 0; mi < 4; mi++) {
#pragma unroll
        for (int ni = 0; ni < 4; ni++) {
            float* p0 = C + (row0 + mi * 16) * N + col0 + ni * 8;
            float* p1 = p0 + 8 * (size_t)N;
            *(float2*)p0 = make_float2(acc[mi][ni][0], acc[mi][ni][1]);
            *(float2*)p1 = make_float2(acc[mi][ni][2], acc[mi][ni][3]);
        }
    }
}

// ---------------------------------------------------------------------------
// HMMA causal flash attention with hi/lo splits (unchanged).
// ---------------------------------------------------------------------------
#define ALD 136
#define AQ_BYTES   (128 * ALD * 2)
#define AKV_BYTES  (64 * ALD * 2)
#define AKV_STAGE  (4 * AKV_BYTES)
#define ATTN_SMEM  (2 * AQ_BYTES + 2 * AKV_STAGE)

__global__ __launch_bounds__(256, 1)
void attn_mma(const __nv_bfloat16* __restrict__ QKVh,
              const __nv_bfloat16* __restrict__ QKVl,
              __nv_bfloat16* __restrict__ outh,
              __nv_bfloat16* __restrict__ outl)
{
    extern __shared__ char smem[];
    const uint32_t s0  = smem_to_u32(smem);
    const uint32_t qhB = s0;
    const uint32_t qlB = s0 + AQ_BYTES;
    const uint32_t kvB = s0 + 2 * AQ_BYTES;

    const int tid = threadIdx.x;
    const int wid = tid >> 5;
    const int l   = tid & 31;
    const int qb  = (int)gridDim.x - 1 - (int)blockIdx.x;
    const int b   = (int)blockIdx.y >> 4;
    const int h   = (int)blockIdx.y & 15;
    const int q0  = qb * 128;
    const size_t rowbase = (size_t)b * T_;
    const float scale = 0.08838834764831843f;

#pragma unroll
    for (int it = 0; it < 16; it++) {
        int idx = tid + it * 256;
        int mat = idx >> 11;
        int r   = (idx >> 4) & 127;
        int c   = idx & 15;
        const __nv_bfloat16* src = (mat ? QKVl : QKVh) +
            (rowbase + q0 + r) * QKV_N + h * HEAD_DIM + c * 8;
        cp_async16((mat ? qlB : qhB) + (uint32_t)(r * ALD + c * 8) * 2, src);
    }

    auto issue_kv = [&](int kv0, int buf) {
        uint32_t base = kvB + (uint32_t)buf * AKV_STAGE;
#pragma unroll
        for (int it = 0; it < 16; it++) {
            int idx = tid + it * 256;
            int m   = idx >> 10;
            int r   = (idx >> 4) & 63;
            int c   = idx & 15;
            const __nv_bfloat16* p = (m & 1) ? QKVl : QKVh;
            int sect = (m >> 1) ? 2 * INNER : INNER;
            const __nv_bfloat16* src = p +
                (rowbase + kv0 + r) * QKV_N + sect + h * HEAD_DIM + c * 8;
            cp_async16(base + (uint32_t)m * AKV_BYTES + (uint32_t)(r * ALD + c * 8) * 2, src);
        }
    };

    const int a_row  = wid * 16 + (l & 15);
    const int a_ch   = (l >> 4) << 3;
    const int g      = l >> 3;
    const int bn_row = ((g >> 1) << 3) + (l & 7);
    const int b_ch   = (g & 1) << 3;
    const int v_kr   = (((l >> 3) & 1) << 3) + (l & 7);
    const int v_nc   = (l >> 4) << 3;

    float o[16][4];
#pragma unroll
    for (int n = 0; n < 16; n++)
#pragma unroll
        for (int e = 0; e < 4; e++) o[n][e] = 0.f;
    float mA = -INFINITY, mB = -INFINITY, lA = 0.f, lB = 0.f;

    const int ntiles = 2 * qb + 2;
    issue_kv(0, 0);
    CP_COMMIT();

    const int row0 = q0 + wid * 16;
    const int r0l  = l >> 2;
    const int rowA = row0 + r0l;
    const int rowB = rowA + 8;

    for (int t = 0; t < ntiles; t++) {
        if (t + 1 < ntiles) {
            issue_kv((t + 1) * 64, (t + 1) & 1);
            CP_COMMIT();
            CP_WAIT(1);
        } else {
            CP_WAIT(0);
        }
        __syncthreads();

        const int kv0 = t * 64;
        const uint32_t st = kvB + (uint32_t)(t & 1) * AKV_STAGE;

        if (kv0 <= row0 + 15) {
            float s[8][4];
#pragma unroll
            for (int n = 0; n < 8; n++)
#pragma unroll
                for (int e = 0; e < 4; e++) s[n][e] = 0.f;

#pragma unroll
            for (int kk = 0; kk < 8; kk++) {
                const int kc = kk * 16;
                uint32_t qa[4], qla[4], kh[8][2], kl[8][2];
                uint32_t qoff = (uint32_t)(a_row * ALD + kc + a_ch) * 2;
                LDSM_X4(qa[0], qa[1], qa[2], qa[3], qhB + qoff);
                LDSM_X4(qla[0], qla[1], qla[2], qla[3], qlB + qoff);
#pragma unroll
                for (int nt = 0; nt < 4; nt++) {
                    uint32_t koff = (uint32_t)((nt * 16 + bn_row) * ALD + kc + b_ch) * 2;
                    LDSM_X4(kh[2 * nt][0], kh[2 * nt][1], kh[2 * nt + 1][0], kh[2 * nt + 1][1],
                            st + koff);
                    LDSM_X4(kl[2 * nt][0], kl[2 * nt][1], kl[2 * nt + 1][0], kl[2 * nt + 1][1],
                            st + AKV_BYTES + koff);
                }
#pragma unroll
                for (int n = 0; n < 8; n++) {
                    mma_bf16(s[n], qa,  kh[n]);
                    mma_bf16(s[n], qla, kh[n]);
                    mma_bf16(s[n], qa,  kl[n]);
                }
            }

#pragma unroll
            for (int n = 0; n < 8; n++)
#pragma unroll
                for (int e = 0; e < 4; e++) s[n][e] *= scale;

            if (kv0 + 63 > row0) {
                const int cb = kv0 + 2 * (l & 3);
#pragma unroll
                for (int n = 0; n < 8; n++) {
                    int c0 = cb + 8 * n;
                    if (c0     > rowA) s[n][0] = -INFINITY;
                    if (c0 + 1 > rowA) s[n][1] = -INFINITY;
                    if (c0     > rowB) s[n][2] = -INFINITY;
                    if (c0 + 1 > rowB) s[n][3] = -INFINITY;
                }
            }

            float mxA = -INFINITY, mxB = -INFINITY;
#pragma unroll
            for (int n = 0; n < 8; n++) {
                mxA = fmaxf(mxA, fmaxf(s[n][0], s[n][1]));
                mxB = fmaxf(mxB, fmaxf(s[n][2], s[n][3]));
            }
#pragma unroll
            for (int off = 1; off < 4; off <<= 1) {
                mxA = fmaxf(mxA, __shfl_xor_sync(0xffffffffu, mxA, off));
                mxB = fmaxf(mxB, __shfl_xor_sync(0xffffffffu, mxB, off));
            }
            float mnA = fmaxf(mA, mxA), mnB = fmaxf(mB, mxB);
            float cA = __expf(mA - mnA), cB = __expf(mB - mnB);
            float rsA = 0.f, rsB = 0.f;
#pragma unroll
            for (int n = 0; n < 8; n++) {
                s[n][0] = __expf(s[n][0] - mnA);
                s[n][1] = __expf(s[n][1] - mnA);
                s[n][2] = __expf(s[n][2] - mnB);
                s[n][3] = __expf(s[n][3] - mnB);
                rsA += s[n][0] + s[n][1];
                rsB += s[n][2] + s[n][3];
            }
#pragma unroll
            for (int off = 1; off < 4; off <<= 1) {
                rsA += __shfl_xor_sync(0xffffffffu, rsA, off);
                rsB += __shfl_xor_sync(0xffffffffu, rsB, off);
            }
            lA = lA * cA + rsA;  mA = mnA;
            lB = lB * cB + rsB;  mB = mnB;
#pragma unroll
            for (int n = 0; n < 16; n++) {
                o[n][0] *= cA; o[n][1] *= cA;
                o[n][2] *= cB; o[n][3] *= cB;
            }

            uint32_t ph[4][4], pl[4][4];
#pragma unroll
            for (int j2 = 0; j2 < 4; j2++) {
#pragma unroll
                for (int hf = 0; hf < 2; hf++) {
                    int j = 2 * j2 + hf;
                    __nv_bfloat16 h0 = __float2bfloat16(s[j][0]);
                    __nv_bfloat16 h1 = __float2bfloat16(s[j][1]);
                    __nv_bfloat16 h2 = __float2bfloat16(s[j][2]);
                    __nv_bfloat16 h3 = __float2bfloat16(s[j][3]);
                    ph[j2][2 * hf]     = pack2(h0, h1);
                    ph[j2][2 * hf + 1] = pack2(h2, h3);
                    pl[j2][2 * hf]     = packf2(s[j][0] - __bfloat162float(h0),
                                                s[j][1] - __bfloat162float(h1));
                    pl[j2][2 * hf + 1] = packf2(s[j][2] - __bfloat162float(h2),
                                                s[j][3] - __bfloat162float(h3));
                }
            }

#pragma unroll
            for (int j2 = 0; j2 < 4; j2++) {
#pragma unroll
                for (int nn = 0; nn < 8; nn++) {
                    uint32_t voff = (uint32_t)((j2 * 16 + v_kr) * ALD + nn * 16 + v_nc) * 2;
                    uint32_t vh01[2], vh23[2], vl01[2], vl23[2];
                    LDSM_X4_T(vh01[0], vh01[1], vh23[0], vh23[1], st + 2 * AKV_BYTES + voff);
                    LDSM_X4_T(vl01[0], vl01[1], vl23[0], vl23[1], st + 3 * AKV_BYTES + voff);
                    mma_bf16(o[2 * nn],     ph[j2], vh01);
                    mma_bf16(o[2 * nn + 1], ph[j2], vh23);
                    mma_bf16(o[2 * nn],     pl[j2], vh01);
                    mma_bf16(o[2 * nn + 1], pl[j2], vh23);
                    mma_bf16(o[2 * nn],     ph[j2], vl01);
                    mma_bf16(o[2 * nn + 1], ph[j2], vl23);
                }
            }
        }
        __syncthreads();
    }

    const float iA = 1.f / lA;
    const float iB = 1.f / lB;
    const size_t bA = (rowbase + rowA) * (size_t)INNER + h * HEAD_DIM + 2 * (l & 3);
    const size_t bB = bA + 8 * (size_t)INNER;
#pragma unroll
    for (int n = 0; n < 16; n++) {
        float vA0 = o[n][0] * iA, vA1 = o[n][1] * iA;
        float vB0 = o[n][2] * iB, vB1 = o[n][3] * iB;
        __nv_bfloat16 hA0 = __float2bfloat16(vA0), hA1 = __float2bfloat16(vA1);
        __nv_bfloat16 hB0 = __float2bfloat16(vB0), hB1 = __float2bfloat16(vB1);
        *(uint32_t*)(outh + bA + 8 * n) = pack2(hA0, hA1);
        *(uint32_t*)(outh + bB + 8 * n) = pack2(hB0, hB1);
        *(uint32_t*)(outl + bA + 8 * n) = packf2(vA0 - __bfloat162float(hA0),
                                                 vA1 - __bfloat162float(hA1));
        *(uint32_t*)(outl + bB + 8 * n) = packf2(vB0 - __bfloat162float(hB0),
                                                 vB1 - __bfloat162float(hB1));
    }
}

// ---------------------------------------------------------------------------
extern "C" void kernel_launch(void* const* d_in, const int* in_sizes, int n_in,
                              void* d_out, int out_size)
{
    const float* x      = (const float*)d_in[0];
    const float* W_qkv  = (const float*)d_in[1];
    const float* W_proj = (const float*)d_in[2];
    float* out = (float*)d_out;

    float *qkv_ptr;
    __nv_bfloat16 *qkvh, *qkvl, *xh, *xl, *wqh, *wql, *wph, *wpl, *ah, *al;
    cudaGetSymbolAddress((void**)&qkv_ptr, g_qkv);
    cudaGetSymbolAddress((void**)&qkvh, g_qkvh);
    cudaGetSymbolAddress((void**)&qkvl, g_qkvl);
    cudaGetSymbolAddress((void**)&xh, g_xh);
    cudaGetSymbolAddress((void**)&xl, g_xl);
    cudaGetSymbolAddress((void**)&wqh, g_wqh);
    cudaGetSymbolAddress((void**)&wql, g_wql);
    cudaGetSymbolAddress((void**)&wph, g_wph);
    cudaGetSymbolAddress((void**)&wpl, g_wpl);
    cudaGetSymbolAddress((void**)&ah, g_ah);
    cudaGetSymbolAddress((void**)&al, g_al);

    cudaFuncSetAttribute(gemm_bf16x3, cudaFuncAttributeMaxDynamicSharedMemorySize,
                         GEMM_SMEM);
    cudaFuncSetAttribute(attn_mma, cudaFuncAttributeMaxDynamicSharedMemorySize,
                         ATTN_SMEM);

    split_kernel<<<(MTOK * DIM / 4) / 256, 256>>>(x, xh, xl, MTOK * DIM / 4);
    split_kernel<<<(QKV_N * DIM / 4) / 256, 256>>>(W_qkv, wqh, wql, QKV_N * DIM / 4);
    split_kernel<<<(INNER * DIM / 4) / 256, 256>>>(W_proj, wph, wpl, INNER * DIM / 4);

    // 1) qkv = x @ W_qkv^T (HMMA, 128x128 tiles, 2 CTAs/SM, 8-chain inner loop)
    gemm_bf16x3<<<dim3(QKV_N / GBN, MTOK / GBM), 256, GEMM_SMEM>>>(
        xh, xl, wqh, wql, qkv_ptr, MTOK, QKV_N, DIM);

    // 2) fused RoPE + split
    rope_split_kernel<<<(3 * B_ * T_ * HEADS * 64) / 256, 256>>>(qkv_ptr, qkvh, qkvl);

    // 3) HMMA causal flash attention
    attn_mma<<<dim3(T_ / 128, B_ * HEADS), 256, ATTN_SMEM>>>(qkvh, qkvl, ah, al);

    // 4) out = attn @ W_proj^T (HMMA)
    gemm_bf16x3<<<dim3(INNER / GBN, MTOK / GBM), 256, GEMM_SMEM>>>(
        ah, al, wph, wpl, out, MTOK, INNER, DIM);
}